// round 6
// baseline (speedup 1.0000x reference)
#include <cuda_runtime.h>
#include <cstdint>

// Problem constants (fixed by the dataset)
#define BB    4
#define NBC   128
#define NINT  4096
#define HID   64

#define NBC_CHK  32
#define NCHUNK   (NBC / NBC_CHK)      // 4

// ---------------------------------------------------------------------------
// Device scratch (allocation-free)
// ---------------------------------------------------------------------------
__device__ float g_avec[BB * NBC * HID];              // a[b][nbc][k]
__device__ float g_c[BB * NINT * HID];                // c[b][i][k] (incl. G0b)
__device__ float g_partial[NCHUNK * BB * NINT];       // per-chunk partial sums

// ---------------------------------------------------------------------------
// tf32 helpers (plain sm_80+ instructions — legal on sm_103 without 'a')
// ---------------------------------------------------------------------------
__device__ __forceinline__ uint32_t cvt_tf32(float x) {
    uint32_t r;
    asm("cvt.rna.tf32.f32 %0, %1;" : "=r"(r) : "f"(x));
    return r;
}

__device__ __forceinline__ void mma_tf32(float& d0, float& d1, float& d2, float& d3,
                                         uint32_t a0, uint32_t a1, uint32_t a2, uint32_t a3,
                                         uint32_t b0, uint32_t b1) {
    asm volatile("mma.sync.aligned.m16n8k8.row.col.f32.tf32.tf32.f32 "
                 "{%0,%1,%2,%3}, {%4,%5,%6,%7}, {%8,%9}, {%0,%1,%2,%3};"
                 : "+f"(d0), "+f"(d1), "+f"(d2), "+f"(d3)
                 : "r"(a0), "r"(a1), "r"(a2), "r"(a3), "r"(b0), "r"(b1));
}

// ---------------------------------------------------------------------------
// Merged prep kernel, 128 threads per block.
//  blocks [0, 256):  prepA — 2 boundary points per block
//  blocks [256, 384): prepC — 128 interior rows per block
// ---------------------------------------------------------------------------
__global__ void __launch_bounds__(128)
prep_kernel(const float* __restrict__ binfo,
            const float* __restrict__ W0, const float* __restrict__ b0,
            const float* __restrict__ W1, const float* __restrict__ b1,
            const float* __restrict__ G0w, const float* __restrict__ G0b,
            const float* __restrict__ coords) {
    __shared__ float sh[2][2][HID];     // [stage][sub][j]
    const int tid = threadIdx.x;

    if (blockIdx.x < 256) {
        // ---- prepA: bf = relu(relu(binfo@W0+b0)@W1+b1);  a = bf @ G0w[:64]
        const int sub = tid >> 6;       // 0..1
        const int j   = tid & 63;
        const int bn  = blockIdx.x * 2 + sub;    // 0..511
        const float* bi = binfo + bn * 3;
        float x0 = bi[0], x1 = bi[1], x2 = bi[2];
        sh[0][sub][j] = fmaxf(
            fmaf(x0, W0[j], fmaf(x1, W0[64 + j], fmaf(x2, W0[128 + j], b0[j]))), 0.0f);
        __syncthreads();
        float s = b1[j];
        #pragma unroll 8
        for (int k = 0; k < HID; k++) s = fmaf(sh[0][sub][k], W1[k * 64 + j], s);
        sh[1][sub][j] = fmaxf(s, 0.0f);
        __syncthreads();
        float a = 0.0f;
        #pragma unroll 8
        for (int k = 0; k < HID; k++) a = fmaf(sh[1][sub][k], G0w[k * 64 + j], a);
        g_avec[bn * 64 + j] = a;
    } else {
        // ---- prepC: c[r][k] = cx*G0w[64][k] + cy*G0w[65][k] + G0b[k]
        float* swx = sh[0][0];
        float* swy = sh[0][1];
        float* sgb = sh[1][0];
        if (tid < HID) {
            swx[tid] = G0w[64 * 64 + tid];
            swy[tid] = G0w[65 * 64 + tid];
            sgb[tid] = G0b[tid];
        }
        __syncthreads();
        int r = (blockIdx.x - 256) * 128 + tid;    // 0..16383
        float cx = coords[(size_t)r * 2 + 0];
        float cy = coords[(size_t)r * 2 + 1];
        float* dst = g_c + (size_t)r * HID;
        #pragma unroll
        for (int kg = 0; kg < 16; kg++) {
            float4 v;
            v.x = fmaf(cx, swx[kg * 4 + 0], fmaf(cy, swy[kg * 4 + 0], sgb[kg * 4 + 0]));
            v.y = fmaf(cx, swx[kg * 4 + 1], fmaf(cy, swy[kg * 4 + 1], sgb[kg * 4 + 1]));
            v.z = fmaf(cx, swx[kg * 4 + 2], fmaf(cy, swy[kg * 4 + 2], sgb[kg * 4 + 2]));
            v.w = fmaf(cx, swx[kg * 4 + 3], fmaf(cy, swy[kg * 4 + 3], sgb[kg * 4 + 3]));
            reinterpret_cast<float4*>(dst)[kg] = v;
        }
    }
}

// ---------------------------------------------------------------------------
// Main kernel.
// grid (32 tiles, 4 batch, 4 nbc-chunks), 256 threads = 8 warps (m16 each),
// 2 CTAs/SM (launch_bounds), 16 warps/SM for tensor-pipe overlap.
// G1b folded into MMA accumulator init. Partials to g_partial.
// ---------------------------------------------------------------------------
#define WSTRIDE 68   // uint2 units per packed k-row; conflict-free per phase

// dynamic smem: s_a 2048 floats (8192B) + s_w 32*68 uint2 (17408B)
#define SMEM_A_BYTES 8192
#define SMEM_TOTAL   (SMEM_A_BYTES + 32 * WSTRIDE * 8)

__global__ void __launch_bounds__(256, 2)
main_kernel(const float* __restrict__ G1w,
            const float* __restrict__ G1b,
            const float* __restrict__ G2w) {
    extern __shared__ char smem[];
    float* s_a = reinterpret_cast<float*>(smem);
    uint2* s_w = reinterpret_cast<uint2*>(smem + SMEM_A_BYTES);

    const int tid   = threadIdx.x;
    const int wid   = tid >> 5;
    const int lane  = tid & 31;
    const int gid   = lane >> 2;    // 0..7
    const int tig   = lane & 3;     // 0..3
    const int tile  = blockIdx.x;   // 0..31
    const int b     = blockIdx.y;   // 0..3
    const int chunk = blockIdx.z;   // 0..3
    const int rowl  = tile * 128 + wid * 16 + gid;     // local row within batch
    const int row0  = b * NINT + rowl;                 // global row (i)

    // --- cooperative smem init ---
    {   // a for this (batch, chunk): 2048 floats
        const float4* src = reinterpret_cast<const float4*>(
            g_avec + ((size_t)b * NBC + chunk * NBC_CHK) * HID);
        float4* dst = reinterpret_cast<float4*>(s_a);
        #pragma unroll
        for (int i = tid; i < 512; i += 256) dst[i] = src[i];
    }
    {   // G1w tf32, packed pairs (k, k+4) per (s,tig) row
        #pragma unroll
        for (int idx = tid; idx < 32 * 64; idx += 256) {
            int prow = idx >> 6;            // 0..31  = s*4 + tig
            int col  = idx & 63;
            int s    = prow >> 2;
            int tg   = prow & 3;
            int k0   = 8 * s + tg;
            uint32_t w0 = cvt_tf32(G1w[k0 * 64 + col]);
            uint32_t w1 = cvt_tf32(G1w[(k0 + 4) * 64 + col]);
            s_w[prow * WSTRIDE + col] = make_uint2(w0, w1);
        }
    }

    // --- loop-invariant registers ---
    float c0r[16], c1r[16];                 // c for rows (row0) and (row0+8)
    {
        const float* cr0 = g_c + (size_t)row0 * HID;
        const float* cr1 = g_c + (size_t)(row0 + 8) * HID;
        #pragma unroll
        for (int s = 0; s < 8; s++) {
            c0r[2 * s + 0] = cr0[8 * s + tig];
            c0r[2 * s + 1] = cr0[8 * s + tig + 4];
            c1r[2 * s + 0] = cr1[8 * s + tig];
            c1r[2 * s + 1] = cr1[8 * s + tig + 4];
        }
    }
    float2 bgv[8];                          // G1b pairs per nb (acc init)
    float2 gwv[8];                          // G2w pairs per nb
    #pragma unroll
    for (int nb = 0; nb < 8; nb++) {
        int j = nb * 8 + 2 * tig;
        bgv[nb] = make_float2(G1b[j], G1b[j + 1]);
        gwv[nb] = make_float2(G2w[j], G2w[j + 1]);
    }
    __syncthreads();

    float acc0 = 0.0f, acc1 = 0.0f;

    for (int nn = 0; nn < NBC_CHK; nn++) {
        const float* arow = s_a + nn * 64;

        // Build A fragments: h1 = relu(a + c), rna-rounded to tf32.
        uint32_t af[8][4];
        #pragma unroll
        for (int s = 0; s < 8; s++) {
            float av0 = arow[8 * s + tig];
            float av4 = arow[8 * s + tig + 4];
            af[s][0] = cvt_tf32(fmaxf(av0 + c0r[2 * s + 0], 0.0f));   // (row gid,   k)
            af[s][1] = cvt_tf32(fmaxf(av0 + c1r[2 * s + 0], 0.0f));   // (row gid+8, k)
            af[s][2] = cvt_tf32(fmaxf(av4 + c0r[2 * s + 1], 0.0f));   // (row gid,   k+4)
            af[s][3] = cvt_tf32(fmaxf(av4 + c1r[2 * s + 1], 0.0f));   // (row gid+8, k+4)
        }

        #pragma unroll
        for (int nb = 0; nb < 8; nb++) {
            // init accumulators with G1b (folds the bias add into the MMA)
            float d0 = bgv[nb].x, d1 = bgv[nb].y, d2 = bgv[nb].x, d3 = bgv[nb].y;
            const int col = nb * 8 + gid;
            #pragma unroll
            for (int s = 0; s < 8; s++) {
                uint2 p = s_w[(s * 4 + tig) * WSTRIDE + col];   // {W[k], W[k+4]}
                mma_tf32(d0, d1, d2, d3, af[s][0], af[s][1], af[s][2], af[s][3], p.x, p.y);
            }
            // epilogue: u[i] += relu(h2) * g2w
            acc0 = fmaf(fmaxf(d0, 0.0f), gwv[nb].x, acc0);
            acc0 = fmaf(fmaxf(d1, 0.0f), gwv[nb].y, acc0);
            acc1 = fmaf(fmaxf(d2, 0.0f), gwv[nb].x, acc1);
            acc1 = fmaf(fmaxf(d3, 0.0f), gwv[nb].y, acc1);
        }
    }

    // reduce over the 4 tig lanes (each holds a disjoint j-subset for same i)
    acc0 += __shfl_xor_sync(0xFFFFFFFFu, acc0, 1);
    acc0 += __shfl_xor_sync(0xFFFFFFFFu, acc0, 2);
    acc1 += __shfl_xor_sync(0xFFFFFFFFu, acc1, 1);
    acc1 += __shfl_xor_sync(0xFFFFFFFFu, acc1, 2);

    if (tig == 0) {
        float* dst = g_partial + ((size_t)chunk * BB + b) * NINT + rowl;
        dst[0] = acc0;
        dst[8] = acc1;
    }
}

// ---------------------------------------------------------------------------
// Final reduction: out[b][i] = (sum over chunks) / NBC + G2b
// ---------------------------------------------------------------------------
__global__ void final_kernel(const float* __restrict__ G2b, float* __restrict__ out) {
    int idx = blockIdx.x * blockDim.x + threadIdx.x;   // 0..16383
    int b  = idx >> 12;
    int ii = idx & 4095;
    float s = 0.0f;
    #pragma unroll
    for (int ch = 0; ch < NCHUNK; ch++)
        s += g_partial[((size_t)ch * BB + b) * NINT + ii];
    out[idx] = s * (1.0f / (float)NBC) + G2b[0];
}

// ---------------------------------------------------------------------------
// Launch.  Inputs (metadata order):
// 0 boundary_info 1 interior_coords 2 W0 3 b0 4 W1 5 b1
// 6 G0w 7 G0b 8 G1w 9 G1b 10 G2w 11 G2b 12 interior_h 13 interior_w
// ---------------------------------------------------------------------------
extern "C" void kernel_launch(void* const* d_in, const int* in_sizes, int n_in,
                              void* d_out, int out_size) {
    const float* binfo  = (const float*)d_in[0];
    const float* coords = (const float*)d_in[1];
    const float* W0     = (const float*)d_in[2];
    const float* b0     = (const float*)d_in[3];
    const float* W1     = (const float*)d_in[4];
    const float* b1     = (const float*)d_in[5];
    const float* G0w    = (const float*)d_in[6];
    const float* G0b    = (const float*)d_in[7];
    const float* G1w    = (const float*)d_in[8];
    const float* G1b    = (const float*)d_in[9];
    const float* G2w    = (const float*)d_in[10];
    const float* G2b    = (const float*)d_in[11];
    float* out          = (float*)d_out;

    cudaFuncSetAttribute(main_kernel, cudaFuncAttributeMaxDynamicSharedMemorySize, SMEM_TOTAL);

    prep_kernel<<<384, 128>>>(binfo, W0, b0, W1, b1, G0w, G0b, coords);
    main_kernel<<<dim3(32, BB, NCHUNK), 256, SMEM_TOTAL>>>(G1w, G1b, G2w);
    final_kernel<<<BB * NINT / 256, 256>>>(G2b, out);
}

// round 7
// speedup vs baseline: 1.0938x; 1.0938x over previous
#include <cuda_runtime.h>
#include <cstdint>

// Problem constants (fixed by the dataset)
#define BB    4
#define NBC   128
#define NINT  4096
#define HID   64

#define NBC_CHK  64
#define NCHUNK   (NBC / NBC_CHK)      // 2

// ---------------------------------------------------------------------------
// Device scratch (allocation-free)
// ---------------------------------------------------------------------------
__device__ float g_avec[BB * NBC * HID];              // a[b][nbc][k]
__device__ float g_c[BB * NINT * HID];                // c[b][i][k] (incl. G0b)
__device__ float g_partial[NCHUNK * BB * NINT];       // per-chunk partial sums

// ---------------------------------------------------------------------------
// tf32 helpers (plain sm_80+ instructions — legal on sm_103 without 'a')
// ---------------------------------------------------------------------------
__device__ __forceinline__ uint32_t cvt_tf32(float x) {
    uint32_t r;
    asm("cvt.rna.tf32.f32 %0, %1;" : "=r"(r) : "f"(x));
    return r;
}

__device__ __forceinline__ void mma_tf32(float& d0, float& d1, float& d2, float& d3,
                                         uint32_t a0, uint32_t a1, uint32_t a2, uint32_t a3,
                                         uint32_t b0, uint32_t b1) {
    asm volatile("mma.sync.aligned.m16n8k8.row.col.f32.tf32.tf32.f32 "
                 "{%0,%1,%2,%3}, {%4,%5,%6,%7}, {%8,%9}, {%0,%1,%2,%3};"
                 : "+f"(d0), "+f"(d1), "+f"(d2), "+f"(d3)
                 : "r"(a0), "r"(a1), "r"(a2), "r"(a3), "r"(b0), "r"(b1));
}

// ---------------------------------------------------------------------------
// Merged prep kernel, 128 threads per block.
//  blocks [0, 256):  prepA — 2 boundary points per block
//  blocks [256, 384): prepC — 128 interior rows per block
// ---------------------------------------------------------------------------
__global__ void __launch_bounds__(128)
prep_kernel(const float* __restrict__ binfo,
            const float* __restrict__ W0, const float* __restrict__ b0,
            const float* __restrict__ W1, const float* __restrict__ b1,
            const float* __restrict__ G0w, const float* __restrict__ G0b,
            const float* __restrict__ coords) {
    __shared__ float sh[2][2][HID];     // [stage][sub][j]
    const int tid = threadIdx.x;

    if (blockIdx.x < 256) {
        // ---- prepA: bf = relu(relu(binfo@W0+b0)@W1+b1);  a = bf @ G0w[:64]
        const int sub = tid >> 6;       // 0..1
        const int j   = tid & 63;
        const int bn  = blockIdx.x * 2 + sub;    // 0..511
        const float* bi = binfo + bn * 3;
        float x0 = bi[0], x1 = bi[1], x2 = bi[2];
        sh[0][sub][j] = fmaxf(
            fmaf(x0, W0[j], fmaf(x1, W0[64 + j], fmaf(x2, W0[128 + j], b0[j]))), 0.0f);
        __syncthreads();
        float s = b1[j];
        #pragma unroll 8
        for (int k = 0; k < HID; k++) s = fmaf(sh[0][sub][k], W1[k * 64 + j], s);
        sh[1][sub][j] = fmaxf(s, 0.0f);
        __syncthreads();
        float a = 0.0f;
        #pragma unroll 8
        for (int k = 0; k < HID; k++) a = fmaf(sh[1][sub][k], G0w[k * 64 + j], a);
        g_avec[bn * 64 + j] = a;
    } else {
        // ---- prepC: c[r][k] = cx*G0w[64][k] + cy*G0w[65][k] + G0b[k]
        float* swx = sh[0][0];
        float* swy = sh[0][1];
        float* sgb = sh[1][0];
        if (tid < HID) {
            swx[tid] = G0w[64 * 64 + tid];
            swy[tid] = G0w[65 * 64 + tid];
            sgb[tid] = G0b[tid];
        }
        __syncthreads();
        int r = (blockIdx.x - 256) * 128 + tid;    // 0..16383
        float cx = coords[(size_t)r * 2 + 0];
        float cy = coords[(size_t)r * 2 + 1];
        float* dst = g_c + (size_t)r * HID;
        #pragma unroll
        for (int kg = 0; kg < 16; kg++) {
            float4 v;
            v.x = fmaf(cx, swx[kg * 4 + 0], fmaf(cy, swy[kg * 4 + 0], sgb[kg * 4 + 0]));
            v.y = fmaf(cx, swx[kg * 4 + 1], fmaf(cy, swy[kg * 4 + 1], sgb[kg * 4 + 1]));
            v.z = fmaf(cx, swx[kg * 4 + 2], fmaf(cy, swy[kg * 4 + 2], sgb[kg * 4 + 2]));
            v.w = fmaf(cx, swx[kg * 4 + 3], fmaf(cy, swy[kg * 4 + 3], sgb[kg * 4 + 3]));
            reinterpret_cast<float4*>(dst)[kg] = v;
        }
    }
}

// ---------------------------------------------------------------------------
// Main kernel.
// grid (32 tiles, 4 batch, 2 nbc-chunks) = 256 CTAs ≈ one full wave at
// 2 CTAs/SM. 256 threads = 8 warps, each warp one m16 row-block.
// G1b/G2w read from smem in the epilogue (register diet for the 128 cap).
// ---------------------------------------------------------------------------
#define WSTRIDE 68   // uint2 units per packed k-row; conflict-free per phase

// dynamic smem: s_a 4096 floats (16384B) + s_w 32*68 uint2 (17408B) + 2*64 floats
#define SMEM_A_BYTES 16384
#define SMEM_W_BYTES (32 * WSTRIDE * 8)
#define SMEM_TOTAL   (SMEM_A_BYTES + SMEM_W_BYTES + 2 * 64 * 4)

__global__ void __launch_bounds__(256, 2)
main_kernel(const float* __restrict__ G1w,
            const float* __restrict__ G1b,
            const float* __restrict__ G2w) {
    extern __shared__ char smem[];
    float* s_a   = reinterpret_cast<float*>(smem);
    uint2* s_w   = reinterpret_cast<uint2*>(smem + SMEM_A_BYTES);
    float* s_g1b = reinterpret_cast<float*>(smem + SMEM_A_BYTES + SMEM_W_BYTES);
    float* s_g2w = s_g1b + 64;

    const int tid   = threadIdx.x;
    const int wid   = tid >> 5;
    const int lane  = tid & 31;
    const int gid   = lane >> 2;    // 0..7
    const int tig   = lane & 3;     // 0..3
    const int tile  = blockIdx.x;   // 0..31
    const int b     = blockIdx.y;   // 0..3
    const int chunk = blockIdx.z;   // 0..1
    const int rowl  = tile * 128 + wid * 16 + gid;     // local row within batch
    const int row0  = b * NINT + rowl;                 // global row (i)

    // --- cooperative smem init ---
    {   // a for this (batch, chunk): 4096 floats
        const float4* src = reinterpret_cast<const float4*>(
            g_avec + ((size_t)b * NBC + chunk * NBC_CHK) * HID);
        float4* dst = reinterpret_cast<float4*>(s_a);
        #pragma unroll
        for (int i = tid; i < 1024; i += 256) dst[i] = src[i];
    }
    {   // G1w tf32, packed pairs (k, k+4) per (s,tig) row
        #pragma unroll
        for (int idx = tid; idx < 32 * 64; idx += 256) {
            int prow = idx >> 6;            // 0..31  = s*4 + tig
            int col  = idx & 63;
            int s    = prow >> 2;
            int tg   = prow & 3;
            int k0   = 8 * s + tg;
            uint32_t w0 = cvt_tf32(G1w[k0 * 64 + col]);
            uint32_t w1 = cvt_tf32(G1w[(k0 + 4) * 64 + col]);
            s_w[prow * WSTRIDE + col] = make_uint2(w0, w1);
        }
    }
    if (tid < 64) { s_g1b[tid] = G1b[tid]; s_g2w[tid] = G2w[tid]; }

    // --- loop-invariant registers: c rows only ---
    float c0r[16], c1r[16];                 // c for rows (row0) and (row0+8)
    {
        const float* cr0 = g_c + (size_t)row0 * HID;
        const float* cr1 = g_c + (size_t)(row0 + 8) * HID;
        #pragma unroll
        for (int s = 0; s < 8; s++) {
            c0r[2 * s + 0] = cr0[8 * s + tig];
            c0r[2 * s + 1] = cr0[8 * s + tig + 4];
            c1r[2 * s + 0] = cr1[8 * s + tig];
            c1r[2 * s + 1] = cr1[8 * s + tig + 4];
        }
    }
    __syncthreads();

    float acc0 = 0.0f, acc1 = 0.0f;

    #pragma unroll 1
    for (int nn = 0; nn < NBC_CHK; nn++) {
        const float* arow = s_a + nn * 64;

        // Build A fragments: h1 = relu(a + c), rna-rounded to tf32.
        uint32_t af[8][4];
        #pragma unroll
        for (int s = 0; s < 8; s++) {
            float av0 = arow[8 * s + tig];
            float av4 = arow[8 * s + tig + 4];
            af[s][0] = cvt_tf32(fmaxf(av0 + c0r[2 * s + 0], 0.0f));   // (row gid,   k)
            af[s][1] = cvt_tf32(fmaxf(av0 + c1r[2 * s + 0], 0.0f));   // (row gid+8, k)
            af[s][2] = cvt_tf32(fmaxf(av4 + c0r[2 * s + 1], 0.0f));   // (row gid,   k+4)
            af[s][3] = cvt_tf32(fmaxf(av4 + c1r[2 * s + 1], 0.0f));   // (row gid+8, k+4)
        }

        #pragma unroll
        for (int nb = 0; nb < 8; nb++) {
            // init accumulators with G1b from smem (4-address broadcast LDS)
            float2 bg = *reinterpret_cast<const float2*>(s_g1b + nb * 8 + 2 * tig);
            float d0 = bg.x, d1 = bg.y, d2 = bg.x, d3 = bg.y;
            const int col = nb * 8 + gid;
            #pragma unroll
            for (int s = 0; s < 8; s++) {
                uint2 p = s_w[(s * 4 + tig) * WSTRIDE + col];   // {W[k], W[k+4]}
                mma_tf32(d0, d1, d2, d3, af[s][0], af[s][1], af[s][2], af[s][3], p.x, p.y);
            }
            // epilogue: u[i] += relu(h2) * g2w
            float2 gw = *reinterpret_cast<const float2*>(s_g2w + nb * 8 + 2 * tig);
            acc0 = fmaf(fmaxf(d0, 0.0f), gw.x, acc0);
            acc0 = fmaf(fmaxf(d1, 0.0f), gw.y, acc0);
            acc1 = fmaf(fmaxf(d2, 0.0f), gw.x, acc1);
            acc1 = fmaf(fmaxf(d3, 0.0f), gw.y, acc1);
        }
    }

    // reduce over the 4 tig lanes (each holds a disjoint j-subset for same i)
    acc0 += __shfl_xor_sync(0xFFFFFFFFu, acc0, 1);
    acc0 += __shfl_xor_sync(0xFFFFFFFFu, acc0, 2);
    acc1 += __shfl_xor_sync(0xFFFFFFFFu, acc1, 1);
    acc1 += __shfl_xor_sync(0xFFFFFFFFu, acc1, 2);

    if (tig == 0) {
        float* dst = g_partial + ((size_t)chunk * BB + b) * NINT + rowl;
        dst[0] = acc0;
        dst[8] = acc1;
    }
}

// ---------------------------------------------------------------------------
// Final reduction: out[b][i] = (sum over chunks) / NBC + G2b
// ---------------------------------------------------------------------------
__global__ void final_kernel(const float* __restrict__ G2b, float* __restrict__ out) {
    int idx = blockIdx.x * blockDim.x + threadIdx.x;   // 0..16383
    int b  = idx >> 12;
    int ii = idx & 4095;
    float s = 0.0f;
    #pragma unroll
    for (int ch = 0; ch < NCHUNK; ch++)
        s += g_partial[((size_t)ch * BB + b) * NINT + ii];
    out[idx] = s * (1.0f / (float)NBC) + G2b[0];
}

// ---------------------------------------------------------------------------
// Launch.  Inputs (metadata order):
// 0 boundary_info 1 interior_coords 2 W0 3 b0 4 W1 5 b1
// 6 G0w 7 G0b 8 G1w 9 G1b 10 G2w 11 G2b 12 interior_h 13 interior_w
// ---------------------------------------------------------------------------
extern "C" void kernel_launch(void* const* d_in, const int* in_sizes, int n_in,
                              void* d_out, int out_size) {
    const float* binfo  = (const float*)d_in[0];
    const float* coords = (const float*)d_in[1];
    const float* W0     = (const float*)d_in[2];
    const float* b0     = (const float*)d_in[3];
    const float* W1     = (const float*)d_in[4];
    const float* b1     = (const float*)d_in[5];
    const float* G0w    = (const float*)d_in[6];
    const float* G0b    = (const float*)d_in[7];
    const float* G1w    = (const float*)d_in[8];
    const float* G1b    = (const float*)d_in[9];
    const float* G2w    = (const float*)d_in[10];
    const float* G2b    = (const float*)d_in[11];
    float* out          = (float*)d_out;

    cudaFuncSetAttribute(main_kernel, cudaFuncAttributeMaxDynamicSharedMemorySize, SMEM_TOTAL);

    prep_kernel<<<384, 128>>>(binfo, W0, b0, W1, b1, G0w, G0b, coords);
    main_kernel<<<dim3(32, BB, NCHUNK), 256, SMEM_TOTAL>>>(G1w, G1b, G2w);
    final_kernel<<<BB * NINT / 256, 256>>>(G2b, out);
}

// round 8
// speedup vs baseline: 1.8398x; 1.6820x over previous
#include <cuda_runtime.h>
#include <cstdint>

// Problem constants (fixed by the dataset)
#define BB    4
#define NBC   128
#define NINT  4096
#define HID   64

// ---------------------------------------------------------------------------
// Device scratch (allocation-free)
// ---------------------------------------------------------------------------
__device__ float g_avec[BB * NBC * HID];              // a[b][nbc][k]
__device__ float g_c[BB * NINT * HID];                // c[b][i][k] (incl. G0b)

// ---------------------------------------------------------------------------
// helpers
// ---------------------------------------------------------------------------
__device__ __forceinline__ uint32_t pack_bf16x2(float lo, float hi) {
    uint32_t r;
    asm("cvt.rn.bf16x2.f32 %0, %1, %2;" : "=r"(r) : "f"(hi), "f"(lo));
    return r;
}

__device__ __forceinline__ void mma_bf16(float& d0, float& d1, float& d2, float& d3,
                                         uint32_t a0, uint32_t a1, uint32_t a2, uint32_t a3,
                                         uint32_t b0, uint32_t b1) {
    asm volatile("mma.sync.aligned.m16n8k16.row.col.f32.bf16.bf16.f32 "
                 "{%0,%1,%2,%3}, {%4,%5,%6,%7}, {%8,%9}, {%0,%1,%2,%3};"
                 : "+f"(d0), "+f"(d1), "+f"(d2), "+f"(d3)
                 : "r"(a0), "r"(a1), "r"(a2), "r"(a3), "r"(b0), "r"(b1));
}

// ---------------------------------------------------------------------------
// Merged prep kernel, 128 threads per block.
//  blocks [0, 256):  prepA — 2 boundary points per block
//  blocks [256, 384): prepC — 128 interior rows per block
// ---------------------------------------------------------------------------
__global__ void __launch_bounds__(128)
prep_kernel(const float* __restrict__ binfo,
            const float* __restrict__ W0, const float* __restrict__ b0,
            const float* __restrict__ W1, const float* __restrict__ b1,
            const float* __restrict__ G0w, const float* __restrict__ G0b,
            const float* __restrict__ coords) {
    __shared__ float sh[2][2][HID];     // [stage][sub][j]
    const int tid = threadIdx.x;

    if (blockIdx.x < 256) {
        // ---- prepA: bf = relu(relu(binfo@W0+b0)@W1+b1);  a = bf @ G0w[:64]
        const int sub = tid >> 6;       // 0..1
        const int j   = tid & 63;
        const int bn  = blockIdx.x * 2 + sub;    // 0..511
        const float* bi = binfo + bn * 3;
        float x0 = bi[0], x1 = bi[1], x2 = bi[2];
        sh[0][sub][j] = fmaxf(
            fmaf(x0, W0[j], fmaf(x1, W0[64 + j], fmaf(x2, W0[128 + j], b0[j]))), 0.0f);
        __syncthreads();
        float s = b1[j];
        #pragma unroll 8
        for (int k = 0; k < HID; k++) s = fmaf(sh[0][sub][k], W1[k * 64 + j], s);
        sh[1][sub][j] = fmaxf(s, 0.0f);
        __syncthreads();
        float a = 0.0f;
        #pragma unroll 8
        for (int k = 0; k < HID; k++) a = fmaf(sh[1][sub][k], G0w[k * 64 + j], a);
        g_avec[bn * 64 + j] = a;
    } else {
        // ---- prepC: c[r][k] = cx*G0w[64][k] + cy*G0w[65][k] + G0b[k]
        float* swx = sh[0][0];
        float* swy = sh[0][1];
        float* sgb = sh[1][0];
        if (tid < HID) {
            swx[tid] = G0w[64 * 64 + tid];
            swy[tid] = G0w[65 * 64 + tid];
            sgb[tid] = G0b[tid];
        }
        __syncthreads();
        int r = (blockIdx.x - 256) * 128 + tid;    // 0..16383
        float cx = coords[(size_t)r * 2 + 0];
        float cy = coords[(size_t)r * 2 + 1];
        float* dst = g_c + (size_t)r * HID;
        #pragma unroll
        for (int kg = 0; kg < 16; kg++) {
            float4 v;
            v.x = fmaf(cx, swx[kg * 4 + 0], fmaf(cy, swy[kg * 4 + 0], sgb[kg * 4 + 0]));
            v.y = fmaf(cx, swx[kg * 4 + 1], fmaf(cy, swy[kg * 4 + 1], sgb[kg * 4 + 1]));
            v.z = fmaf(cx, swx[kg * 4 + 2], fmaf(cy, swy[kg * 4 + 2], sgb[kg * 4 + 2]));
            v.w = fmaf(cx, swx[kg * 4 + 3], fmaf(cy, swy[kg * 4 + 3], sgb[kg * 4 + 3]));
            reinterpret_cast<float4*>(dst)[kg] = v;
        }
    }
}

// ---------------------------------------------------------------------------
// Main kernel (bf16 m16n8k16).
// grid (32 tiles, 4 batch) = 128 CTAs, single wave. 256 threads = 8 warps,
// each warp one m16 row-block over the full NBC=128 loop. Direct output.
//
// Per nn: A-frags (h1 = relu(a+c), rn->bf16x2) built in regs; B (G1w bf16,
// packed {k,k+1 | k+8,k+9}) one LDS.64 per MMA; D init = G1b; epilogue
// relu(D)*G2w into 2 per-thread accumulators.
// ---------------------------------------------------------------------------
#define WSTRIDE 68   // uint2 units per packed row; conflict-free per 16-lane phase

// dynamic smem: s_a 8192 floats (32768B) + s_w 16*68 uint2 (8704B)
#define SMEM_A_BYTES 32768
#define SMEM_TOTAL   (SMEM_A_BYTES + 16 * WSTRIDE * 8)

__global__ void __launch_bounds__(256, 1)
main_kernel(const float* __restrict__ G1w,
            const float* __restrict__ G1b,
            const float* __restrict__ G2w,
            const float* __restrict__ G2b,
            float* __restrict__ out) {
    extern __shared__ char smem[];
    float* s_a = reinterpret_cast<float*>(smem);
    uint2* s_w = reinterpret_cast<uint2*>(smem + SMEM_A_BYTES);

    const int tid  = threadIdx.x;
    const int wid  = tid >> 5;
    const int lane = tid & 31;
    const int gid  = lane >> 2;     // 0..7
    const int tig  = lane & 3;      // 0..3
    const int tile = blockIdx.x;    // 0..31
    const int b    = blockIdx.y;    // 0..3
    const int row0 = b * NINT + tile * 128 + wid * 16 + gid;   // global row (i)

    // --- cooperative smem init ---
    {   // a for this batch: 8192 floats
        const float4* src = reinterpret_cast<const float4*>(g_avec + (size_t)b * NBC * HID);
        float4* dst = reinterpret_cast<float4*>(s_a);
        #pragma unroll
        for (int i = tid; i < 2048; i += 256) dst[i] = src[i];
    }
    {   // G1w -> bf16, packed per (s,tg): {W[k0],W[k0+1]} , {W[k0+8],W[k0+9]}
        #pragma unroll
        for (int idx = tid; idx < 16 * 64; idx += 256) {
            int prow = idx >> 6;            // 0..15 = s*4 + tg
            int col  = idx & 63;
            int s    = prow >> 2;
            int tg   = prow & 3;
            int k0   = 16 * s + 2 * tg;
            uint32_t w0 = pack_bf16x2(G1w[k0 * 64 + col],       G1w[(k0 + 1) * 64 + col]);
            uint32_t w1 = pack_bf16x2(G1w[(k0 + 8) * 64 + col], G1w[(k0 + 9) * 64 + col]);
            s_w[prow * WSTRIDE + col] = make_uint2(w0, w1);
        }
    }

    // --- loop-invariant registers ---
    // c for rows row0 and row0+8 at k = 16s+2tig{,+1} and 16s+2tig+8{,+9}
    float c0r[16], c1r[16];
    {
        const float* cr0 = g_c + (size_t)row0 * HID;
        const float* cr1 = cr0 + 8 * HID;
        #pragma unroll
        for (int s = 0; s < 4; s++) {
            float2 p0 = *reinterpret_cast<const float2*>(cr0 + 16 * s + 2 * tig);
            float2 p1 = *reinterpret_cast<const float2*>(cr0 + 16 * s + 2 * tig + 8);
            float2 q0 = *reinterpret_cast<const float2*>(cr1 + 16 * s + 2 * tig);
            float2 q1 = *reinterpret_cast<const float2*>(cr1 + 16 * s + 2 * tig + 8);
            c0r[4 * s + 0] = p0.x; c0r[4 * s + 1] = p0.y;
            c0r[4 * s + 2] = p1.x; c0r[4 * s + 3] = p1.y;
            c1r[4 * s + 0] = q0.x; c1r[4 * s + 1] = q0.y;
            c1r[4 * s + 2] = q1.x; c1r[4 * s + 3] = q1.y;
        }
    }
    // G1b / G2w pairs per nb (j = nb*8 + 2*tig)
    float2 bgv[8], gwv[8];
    #pragma unroll
    for (int nb = 0; nb < 8; nb++) {
        int j = nb * 8 + 2 * tig;
        bgv[nb] = *reinterpret_cast<const float2*>(G1b + j);
        gwv[nb] = *reinterpret_cast<const float2*>(G2w + j);
    }
    __syncthreads();

    float acc0 = 0.0f, acc1 = 0.0f;

    #pragma unroll 1
    for (int nn = 0; nn < NBC; nn++) {
        const float* arow = s_a + nn * 64;

        // Build A fragments: h1 = relu(a + c) -> bf16x2 (rn, unbiased)
        uint32_t a0[4], a1[4], a2[4], a3[4];
        #pragma unroll
        for (int s = 0; s < 4; s++) {
            float2 av = *reinterpret_cast<const float2*>(arow + 16 * s + 2 * tig);
            float2 aw = *reinterpret_cast<const float2*>(arow + 16 * s + 2 * tig + 8);
            a0[s] = pack_bf16x2(fmaxf(av.x + c0r[4 * s + 0], 0.0f),
                                fmaxf(av.y + c0r[4 * s + 1], 0.0f));   // row gid,   k,k+1
            a1[s] = pack_bf16x2(fmaxf(av.x + c1r[4 * s + 0], 0.0f),
                                fmaxf(av.y + c1r[4 * s + 1], 0.0f));   // row gid+8, k,k+1
            a2[s] = pack_bf16x2(fmaxf(aw.x + c0r[4 * s + 2], 0.0f),
                                fmaxf(aw.y + c0r[4 * s + 3], 0.0f));   // row gid,   k+8,k+9
            a3[s] = pack_bf16x2(fmaxf(aw.x + c1r[4 * s + 2], 0.0f),
                                fmaxf(aw.y + c1r[4 * s + 3], 0.0f));   // row gid+8, k+8,k+9
        }

        #pragma unroll
        for (int nb = 0; nb < 8; nb++) {
            // init accumulators with G1b (folds the bias add into the MMA)
            float d0 = bgv[nb].x, d1 = bgv[nb].y, d2 = bgv[nb].x, d3 = bgv[nb].y;
            const int col = nb * 8 + gid;
            #pragma unroll
            for (int s = 0; s < 4; s++) {
                uint2 p = s_w[(s * 4 + tig) * WSTRIDE + col];
                mma_bf16(d0, d1, d2, d3, a0[s], a1[s], a2[s], a3[s], p.x, p.y);
            }
            // epilogue: u[i] += relu(h2) * g2w
            acc0 = fmaf(fmaxf(d0, 0.0f), gwv[nb].x, acc0);
            acc0 = fmaf(fmaxf(d1, 0.0f), gwv[nb].y, acc0);
            acc1 = fmaf(fmaxf(d2, 0.0f), gwv[nb].x, acc1);
            acc1 = fmaf(fmaxf(d3, 0.0f), gwv[nb].y, acc1);
        }
    }

    // reduce over the 4 tig lanes (each holds a disjoint j-subset for same i)
    acc0 += __shfl_xor_sync(0xFFFFFFFFu, acc0, 1);
    acc0 += __shfl_xor_sync(0xFFFFFFFFu, acc0, 2);
    acc1 += __shfl_xor_sync(0xFFFFFFFFu, acc1, 1);
    acc1 += __shfl_xor_sync(0xFFFFFFFFu, acc1, 2);

    if (tig == 0) {
        float g2 = G2b[0];
        out[row0]     = acc0 * (1.0f / (float)NBC) + g2;
        out[row0 + 8] = acc1 * (1.0f / (float)NBC) + g2;
    }
}

// ---------------------------------------------------------------------------
// Launch.  Inputs (metadata order):
// 0 boundary_info 1 interior_coords 2 W0 3 b0 4 W1 5 b1
// 6 G0w 7 G0b 8 G1w 9 G1b 10 G2w 11 G2b 12 interior_h 13 interior_w
// ---------------------------------------------------------------------------
extern "C" void kernel_launch(void* const* d_in, const int* in_sizes, int n_in,
                              void* d_out, int out_size) {
    const float* binfo  = (const float*)d_in[0];
    const float* coords = (const float*)d_in[1];
    const float* W0     = (const float*)d_in[2];
    const float* b0     = (const float*)d_in[3];
    const float* W1     = (const float*)d_in[4];
    const float* b1     = (const float*)d_in[5];
    const float* G0w    = (const float*)d_in[6];
    const float* G0b    = (const float*)d_in[7];
    const float* G1w    = (const float*)d_in[8];
    const float* G1b    = (const float*)d_in[9];
    const float* G2w    = (const float*)d_in[10];
    const float* G2b    = (const float*)d_in[11];
    float* out          = (float*)d_out;

    cudaFuncSetAttribute(main_kernel, cudaFuncAttributeMaxDynamicSharedMemorySize, SMEM_TOTAL);

    prep_kernel<<<384, 128>>>(binfo, W0, b0, W1, b1, G0w, G0b, coords);
    main_kernel<<<dim3(32, BB), 256, SMEM_TOTAL>>>(G1w, G1b, G2w, G2b, out);
}

// round 9
// speedup vs baseline: 1.9660x; 1.0686x over previous
#include <cuda_runtime.h>
#include <cstdint>

// Problem constants (fixed by the dataset)
#define BB    4
#define NBC   128
#define NINT  4096
#define HID   64

// ---------------------------------------------------------------------------
// Device scratch (allocation-free)
// ---------------------------------------------------------------------------
__device__ float g_avec[BB * NBC * HID];              // a[b][nbc][k]

// ---------------------------------------------------------------------------
// helpers
// ---------------------------------------------------------------------------
__device__ __forceinline__ uint32_t pack_bf16x2(float lo, float hi) {
    uint32_t r;
    asm("cvt.rn.bf16x2.f32 %0, %1, %2;" : "=r"(r) : "f"(hi), "f"(lo));
    return r;
}

__device__ __forceinline__ void mma_bf16(float& d0, float& d1, float& d2, float& d3,
                                         uint32_t a0, uint32_t a1, uint32_t a2, uint32_t a3,
                                         uint32_t b0, uint32_t b1) {
    asm volatile("mma.sync.aligned.m16n8k16.row.col.f32.bf16.bf16.f32 "
                 "{%0,%1,%2,%3}, {%4,%5,%6,%7}, {%8,%9}, {%0,%1,%2,%3};"
                 : "+f"(d0), "+f"(d1), "+f"(d2), "+f"(d3)
                 : "r"(a0), "r"(a1), "r"(a2), "r"(a3), "r"(b0), "r"(b1));
}

// ---------------------------------------------------------------------------
// prepA kernel: per (b,nbc): bf = relu(relu(binfo@W0+b0)@W1+b1); a = bf@G0w[:64]
// 256 blocks x 128 threads (2 boundary points per block)
// ---------------------------------------------------------------------------
__global__ void __launch_bounds__(128)
prepA_kernel(const float* __restrict__ binfo,
             const float* __restrict__ W0, const float* __restrict__ b0,
             const float* __restrict__ W1, const float* __restrict__ b1,
             const float* __restrict__ G0w) {
    __shared__ float sh[2][2][HID];     // [stage][sub][j]
    const int tid = threadIdx.x;
    const int sub = tid >> 6;       // 0..1
    const int j   = tid & 63;
    const int bn  = blockIdx.x * 2 + sub;    // 0..511
    const float* bi = binfo + bn * 3;
    float x0 = bi[0], x1 = bi[1], x2 = bi[2];
    sh[0][sub][j] = fmaxf(
        fmaf(x0, W0[j], fmaf(x1, W0[64 + j], fmaf(x2, W0[128 + j], b0[j]))), 0.0f);
    __syncthreads();
    float s = b1[j];
    #pragma unroll 8
    for (int k = 0; k < HID; k++) s = fmaf(sh[0][sub][k], W1[k * 64 + j], s);
    sh[1][sub][j] = fmaxf(s, 0.0f);
    __syncthreads();
    float a = 0.0f;
    #pragma unroll 8
    for (int k = 0; k < HID; k++) a = fmaf(sh[1][sub][k], G0w[k * 64 + j], a);
    g_avec[bn * 64 + j] = a;
}

// ---------------------------------------------------------------------------
// Main kernel (bf16 m16n8k16, B in registers).
// grid (32 tiles, 4 batch) = 128 CTAs, single wave. 256 threads = 8 warps,
// each warp one m16 row-block over the full NBC=128 loop. Direct output.
//
// B-fragments (G1w bf16) are loop-invariant: staged once through smem into
// 32 uint2 registers per thread. c = coords@G0w[64:]+G0b computed in-register
// from smem-cached weight columns (prepC kernel and g_c scratch eliminated).
// ---------------------------------------------------------------------------
#define WSTRIDE 68   // uint2 units per packed row (staging only)

// dynamic smem: s_a 8192 floats (32768B) + s_w 16*68 uint2 (8704B) + 3*64 floats
#define SMEM_A_BYTES 32768
#define SMEM_W_BYTES (16 * WSTRIDE * 8)
#define SMEM_TOTAL   (SMEM_A_BYTES + SMEM_W_BYTES + 3 * 64 * 4)

__global__ void __launch_bounds__(256, 1)
main_kernel(const float* __restrict__ G1w,
            const float* __restrict__ G1b,
            const float* __restrict__ G2w,
            const float* __restrict__ G2b,
            const float* __restrict__ coords,
            const float* __restrict__ G0w,
            const float* __restrict__ G0b,
            float* __restrict__ out) {
    extern __shared__ char smem[];
    float* s_a  = reinterpret_cast<float*>(smem);
    uint2* s_w  = reinterpret_cast<uint2*>(smem + SMEM_A_BYTES);
    float* s_wx = reinterpret_cast<float*>(smem + SMEM_A_BYTES + SMEM_W_BYTES);
    float* s_wy = s_wx + 64;
    float* s_gb = s_wy + 64;

    const int tid  = threadIdx.x;
    const int wid  = tid >> 5;
    const int lane = tid & 31;
    const int gid  = lane >> 2;     // 0..7
    const int tig  = lane & 3;      // 0..3
    const int tile = blockIdx.x;    // 0..31
    const int b    = blockIdx.y;    // 0..3
    const int row0 = b * NINT + tile * 128 + wid * 16 + gid;   // global row (i)

    // --- cooperative smem init ---
    {   // a for this batch: 8192 floats
        const float4* src = reinterpret_cast<const float4*>(g_avec + (size_t)b * NBC * HID);
        float4* dst = reinterpret_cast<float4*>(s_a);
        #pragma unroll
        for (int i = tid; i < 2048; i += 256) dst[i] = src[i];
    }
    {   // G1w -> bf16, packed per (s,tg): {W[k0],W[k0+1]} , {W[k0+8],W[k0+9]}
        #pragma unroll
        for (int idx = tid; idx < 16 * 64; idx += 256) {
            int prow = idx >> 6;            // 0..15 = s*4 + tg
            int col  = idx & 63;
            int s    = prow >> 2;
            int tg   = prow & 3;
            int k0   = 16 * s + 2 * tg;
            uint32_t w0 = pack_bf16x2(G1w[k0 * 64 + col],       G1w[(k0 + 1) * 64 + col]);
            uint32_t w1 = pack_bf16x2(G1w[(k0 + 8) * 64 + col], G1w[(k0 + 9) * 64 + col]);
            s_w[prow * WSTRIDE + col] = make_uint2(w0, w1);
        }
    }
    if (tid < 64) {
        s_wx[tid] = G0w[64 * 64 + tid];
        s_wy[tid] = G0w[65 * 64 + tid];
        s_gb[tid] = G0b[tid];
    }
    __syncthreads();

    // --- loop-invariant registers ---
    // c for rows row0 and row0+8 at k = 16s+2tig{,+1} and 16s+2tig+8{,+9}
    float c0r[16], c1r[16];
    {
        float cx0 = coords[(size_t)row0 * 2 + 0];
        float cy0 = coords[(size_t)row0 * 2 + 1];
        float cx1 = coords[(size_t)(row0 + 8) * 2 + 0];
        float cy1 = coords[(size_t)(row0 + 8) * 2 + 1];
        #pragma unroll
        for (int s = 0; s < 4; s++) {
            #pragma unroll
            for (int e = 0; e < 4; e++) {
                int k = 16 * s + 2 * tig + (e & 1) + ((e >> 1) << 3);  // +0,+1,+8,+9
                float wx = s_wx[k], wy = s_wy[k], gb = s_gb[k];
                c0r[4 * s + e] = fmaf(cx0, wx, fmaf(cy0, wy, gb));
                c1r[4 * s + e] = fmaf(cx1, wx, fmaf(cy1, wy, gb));
            }
        }
    }
    // B fragments hoisted into registers (loop-invariant): 32 x uint2
    uint2 bw[8][4];
    #pragma unroll
    for (int nb = 0; nb < 8; nb++) {
        const int col = nb * 8 + gid;
        #pragma unroll
        for (int s = 0; s < 4; s++)
            bw[nb][s] = s_w[(s * 4 + tig) * WSTRIDE + col];
    }
    // G1b / G2w pairs per nb (j = nb*8 + 2*tig)
    float2 bgv[8], gwv[8];
    #pragma unroll
    for (int nb = 0; nb < 8; nb++) {
        int j = nb * 8 + 2 * tig;
        bgv[nb] = *reinterpret_cast<const float2*>(G1b + j);
        gwv[nb] = *reinterpret_cast<const float2*>(G2w + j);
    }

    float acc0 = 0.0f, acc1 = 0.0f;

    #pragma unroll 1
    for (int nn = 0; nn < NBC; nn++) {
        const float* arow = s_a + nn * 64;

        // Build A fragments: h1 = relu(a + c) -> bf16x2 (rn, unbiased)
        uint32_t a0[4], a1[4], a2[4], a3[4];
        #pragma unroll
        for (int s = 0; s < 4; s++) {
            float2 av = *reinterpret_cast<const float2*>(arow + 16 * s + 2 * tig);
            float2 aw = *reinterpret_cast<const float2*>(arow + 16 * s + 2 * tig + 8);
            a0[s] = pack_bf16x2(fmaxf(av.x + c0r[4 * s + 0], 0.0f),
                                fmaxf(av.y + c0r[4 * s + 1], 0.0f));   // row gid,   k,k+1
            a1[s] = pack_bf16x2(fmaxf(av.x + c1r[4 * s + 0], 0.0f),
                                fmaxf(av.y + c1r[4 * s + 1], 0.0f));   // row gid+8, k,k+1
            a2[s] = pack_bf16x2(fmaxf(aw.x + c0r[4 * s + 2], 0.0f),
                                fmaxf(aw.y + c0r[4 * s + 3], 0.0f));   // row gid,   k+8,k+9
            a3[s] = pack_bf16x2(fmaxf(aw.x + c1r[4 * s + 2], 0.0f),
                                fmaxf(aw.y + c1r[4 * s + 3], 0.0f));   // row gid+8, k+8,k+9
        }

        #pragma unroll
        for (int nb = 0; nb < 8; nb++) {
            // init accumulators with G1b (folds the bias add into the MMA)
            float d0 = bgv[nb].x, d1 = bgv[nb].y, d2 = bgv[nb].x, d3 = bgv[nb].y;
            #pragma unroll
            for (int s = 0; s < 4; s++)
                mma_bf16(d0, d1, d2, d3, a0[s], a1[s], a2[s], a3[s],
                         bw[nb][s].x, bw[nb][s].y);
            // epilogue: u[i] += relu(h2) * g2w
            acc0 = fmaf(fmaxf(d0, 0.0f), gwv[nb].x, acc0);
            acc0 = fmaf(fmaxf(d1, 0.0f), gwv[nb].y, acc0);
            acc1 = fmaf(fmaxf(d2, 0.0f), gwv[nb].x, acc1);
            acc1 = fmaf(fmaxf(d3, 0.0f), gwv[nb].y, acc1);
        }
    }

    // reduce over the 4 tig lanes (each holds a disjoint j-subset for same i)
    acc0 += __shfl_xor_sync(0xFFFFFFFFu, acc0, 1);
    acc0 += __shfl_xor_sync(0xFFFFFFFFu, acc0, 2);
    acc1 += __shfl_xor_sync(0xFFFFFFFFu, acc1, 1);
    acc1 += __shfl_xor_sync(0xFFFFFFFFu, acc1, 2);

    if (tig == 0) {
        float g2 = G2b[0];
        out[row0]     = acc0 * (1.0f / (float)NBC) + g2;
        out[row0 + 8] = acc1 * (1.0f / (float)NBC) + g2;
    }
}

// ---------------------------------------------------------------------------
// Launch.  Inputs (metadata order):
// 0 boundary_info 1 interior_coords 2 W0 3 b0 4 W1 5 b1
// 6 G0w 7 G0b 8 G1w 9 G1b 10 G2w 11 G2b 12 interior_h 13 interior_w
// ---------------------------------------------------------------------------
extern "C" void kernel_launch(void* const* d_in, const int* in_sizes, int n_in,
                              void* d_out, int out_size) {
    const float* binfo  = (const float*)d_in[0];
    const float* coords = (const float*)d_in[1];
    const float* W0     = (const float*)d_in[2];
    const float* b0     = (const float*)d_in[3];
    const float* W1     = (const float*)d_in[4];
    const float* b1     = (const float*)d_in[5];
    const float* G0w    = (const float*)d_in[6];
    const float* G0b    = (const float*)d_in[7];
    const float* G1w    = (const float*)d_in[8];
    const float* G1b    = (const float*)d_in[9];
    const float* G2w    = (const float*)d_in[10];
    const float* G2b    = (const float*)d_in[11];
    float* out          = (float*)d_out;

    cudaFuncSetAttribute(main_kernel, cudaFuncAttributeMaxDynamicSharedMemorySize, SMEM_TOTAL);

    prepA_kernel<<<256, 128>>>(binfo, W0, b0, W1, b1, G0w);
    main_kernel<<<dim3(32, BB), 256, SMEM_TOTAL>>>(G1w, G1b, G2w, G2b, coords, G0w, G0b, out);
}

// round 10
// speedup vs baseline: 2.0113x; 1.0230x over previous
#include <cuda_runtime.h>
#include <cstdint>

// Problem constants (fixed by the dataset)
#define BB    4
#define NBC   128
#define NINT  4096
#define HID   64

#define NBC_CHK  64
#define NCHUNK   (NBC / NBC_CHK)      // 2

// ---------------------------------------------------------------------------
// Device scratch (allocation-free)
// ---------------------------------------------------------------------------
__device__ float g_avec[BB * NBC * HID];              // a[b][nbc][k]
__device__ float g_partial[NCHUNK * BB * NINT];       // per-chunk partial sums

// ---------------------------------------------------------------------------
// helpers
// ---------------------------------------------------------------------------
__device__ __forceinline__ uint32_t pack_bf16x2(float lo, float hi) {
    uint32_t r;
    asm("cvt.rn.bf16x2.f32 %0, %1, %2;" : "=r"(r) : "f"(hi), "f"(lo));
    return r;
}
__device__ __forceinline__ uint32_t add_bf16x2(uint32_t a, uint32_t b) {
    uint32_t r;
    asm("add.rn.bf16x2 %0, %1, %2;" : "=r"(r) : "r"(a), "r"(b));
    return r;
}
__device__ __forceinline__ uint32_t relu_bf16x2(uint32_t a) {
    uint32_t r;
    asm("max.bf16x2 %0, %1, %2;" : "=r"(r) : "r"(a), "r"(0u));
    return r;
}

__device__ __forceinline__ void mma_bf16(float& d0, float& d1, float& d2, float& d3,
                                         uint32_t a0, uint32_t a1, uint32_t a2, uint32_t a3,
                                         uint32_t b0, uint32_t b1) {
    asm volatile("mma.sync.aligned.m16n8k16.row.col.f32.bf16.bf16.f32 "
                 "{%0,%1,%2,%3}, {%4,%5,%6,%7}, {%8,%9}, {%0,%1,%2,%3};"
                 : "+f"(d0), "+f"(d1), "+f"(d2), "+f"(d3)
                 : "r"(a0), "r"(a1), "r"(a2), "r"(a3), "r"(b0), "r"(b1));
}

// ---------------------------------------------------------------------------
// prepA kernel: per (b,nbc): bf = relu(relu(binfo@W0+b0)@W1+b1); a = bf@G0w[:64]
// 256 blocks x 128 threads (2 boundary points per block)
// ---------------------------------------------------------------------------
__global__ void __launch_bounds__(128)
prepA_kernel(const float* __restrict__ binfo,
             const float* __restrict__ W0, const float* __restrict__ b0,
             const float* __restrict__ W1, const float* __restrict__ b1,
             const float* __restrict__ G0w) {
    __shared__ float sh[2][2][HID];     // [stage][sub][j]
    const int tid = threadIdx.x;
    const int sub = tid >> 6;       // 0..1
    const int j   = tid & 63;
    const int bn  = blockIdx.x * 2 + sub;    // 0..511
    const float* bi = binfo + bn * 3;
    float x0 = bi[0], x1 = bi[1], x2 = bi[2];
    sh[0][sub][j] = fmaxf(
        fmaf(x0, W0[j], fmaf(x1, W0[64 + j], fmaf(x2, W0[128 + j], b0[j]))), 0.0f);
    __syncthreads();
    float s = b1[j];
    #pragma unroll 8
    for (int k = 0; k < HID; k++) s = fmaf(sh[0][sub][k], W1[k * 64 + j], s);
    sh[1][sub][j] = fmaxf(s, 0.0f);
    __syncthreads();
    float a = 0.0f;
    #pragma unroll 8
    for (int k = 0; k < HID; k++) a = fmaf(sh[1][sub][k], G0w[k * 64 + j], a);
    g_avec[bn * 64 + j] = a;
}

// ---------------------------------------------------------------------------
// Main kernel (bf16 m16n8k16; packed bf16x2 A-build; B in registers).
// grid (32 tiles, 4 batch, 2 nbc-chunks) = 256 CTAs, 2 CTAs/SM target.
// 256 threads = 8 warps, each warp one m16 row-block, 64 nbc iters.
// ---------------------------------------------------------------------------
#define WSTRIDE 68   // uint2 units per packed row (staging only)

// smem: s_ap 64*32 uint32 (8192B) | s_w 16*68 uint2 (8704B) |
//       s_g1b/s_g2w 2*64 f (512B) | s_wx/s_wy/s_gb 3*64 f (768B)
#define SMEM_AP_BYTES 8192
#define SMEM_W_BYTES  (16 * WSTRIDE * 8)
#define SMEM_GB_OFF   (SMEM_AP_BYTES + SMEM_W_BYTES)
#define SMEM_TOTAL    (SMEM_GB_OFF + 2 * 64 * 4 + 3 * 64 * 4)

__global__ void __launch_bounds__(256, 2)
main_kernel(const float* __restrict__ G1w,
            const float* __restrict__ G1b,
            const float* __restrict__ G2w,
            const float* __restrict__ coords,
            const float* __restrict__ G0w,
            const float* __restrict__ G0b) {
    extern __shared__ char smem[];
    uint32_t* s_ap = reinterpret_cast<uint32_t*>(smem);
    uint2*    s_w  = reinterpret_cast<uint2*>(smem + SMEM_AP_BYTES);
    float*    s_g1b = reinterpret_cast<float*>(smem + SMEM_GB_OFF);
    float*    s_g2w = s_g1b + 64;
    float*    s_wx  = s_g2w + 64;
    float*    s_wy  = s_wx + 64;
    float*    s_gb  = s_wy + 64;

    const int tid   = threadIdx.x;
    const int wid   = tid >> 5;
    const int lane  = tid & 31;
    const int gid   = lane >> 2;    // 0..7
    const int tig   = lane & 3;     // 0..3
    const int tile  = blockIdx.x;   // 0..31
    const int b     = blockIdx.y;   // 0..3
    const int chunk = blockIdx.z;   // 0..1
    const int rowl  = tile * 128 + wid * 16 + gid;   // local row within batch
    const int row0  = b * NINT + rowl;               // global row (i)

    // --- cooperative smem init ---
    {   // a for this (batch, chunk): 4096 floats -> 2048 bf16x2
        const float2* src = reinterpret_cast<const float2*>(
            g_avec + ((size_t)b * NBC + chunk * NBC_CHK) * HID);
        #pragma unroll
        for (int i = tid; i < 2048; i += 256) {
            float2 v = src[i];
            s_ap[i] = pack_bf16x2(v.x, v.y);
        }
    }
    {   // G1w -> bf16, packed per (s,tg): {W[k0],W[k0+1]} , {W[k0+8],W[k0+9]}
        #pragma unroll
        for (int idx = tid; idx < 16 * 64; idx += 256) {
            int prow = idx >> 6;            // 0..15 = s*4 + tg
            int col  = idx & 63;
            int s    = prow >> 2;
            int tg   = prow & 3;
            int k0   = 16 * s + 2 * tg;
            uint32_t w0 = pack_bf16x2(G1w[k0 * 64 + col],       G1w[(k0 + 1) * 64 + col]);
            uint32_t w1 = pack_bf16x2(G1w[(k0 + 8) * 64 + col], G1w[(k0 + 9) * 64 + col]);
            s_w[prow * WSTRIDE + col] = make_uint2(w0, w1);
        }
    }
    if (tid < 64) {
        s_g1b[tid] = G1b[tid];
        s_g2w[tid] = G2w[tid];
        s_wx[tid]  = G0w[64 * 64 + tid];
        s_wy[tid]  = G0w[65 * 64 + tid];
        s_gb[tid]  = G0b[tid];
    }
    __syncthreads();

    // --- loop-invariant registers ---
    // c packed bf16x2 for rows row0 / row0+8 at k-pairs (16s+2tig, +1) and (+8, +9)
    uint32_t cp0[8], cp1[8];
    {
        float cx0 = coords[(size_t)row0 * 2 + 0];
        float cy0 = coords[(size_t)row0 * 2 + 1];
        float cx1 = coords[(size_t)(row0 + 8) * 2 + 0];
        float cy1 = coords[(size_t)(row0 + 8) * 2 + 1];
        #pragma unroll
        for (int s = 0; s < 4; s++) {
            #pragma unroll
            for (int h = 0; h < 2; h++) {          // h=0: k,k+1 ; h=1: k+8,k+9
                int k = 16 * s + 2 * tig + 8 * h;
                float wxa = s_wx[k],     wya = s_wy[k],     gba = s_gb[k];
                float wxb = s_wx[k + 1], wyb = s_wy[k + 1], gbb = s_gb[k + 1];
                cp0[2 * s + h] = pack_bf16x2(fmaf(cx0, wxa, fmaf(cy0, wya, gba)),
                                             fmaf(cx0, wxb, fmaf(cy0, wyb, gbb)));
                cp1[2 * s + h] = pack_bf16x2(fmaf(cx1, wxa, fmaf(cy1, wya, gba)),
                                             fmaf(cx1, wxb, fmaf(cy1, wyb, gbb)));
            }
        }
    }
    // B fragments hoisted into registers (loop-invariant): 32 x uint2
    uint2 bw[8][4];
    #pragma unroll
    for (int nb = 0; nb < 8; nb++) {
        const int col = nb * 8 + gid;
        #pragma unroll
        for (int s = 0; s < 4; s++)
            bw[nb][s] = s_w[(s * 4 + tig) * WSTRIDE + col];
    }

    float acc0 = 0.0f, acc1 = 0.0f;

    #pragma unroll 1
    for (int nn = 0; nn < NBC_CHK; nn++) {
        const uint32_t* ar = s_ap + nn * 32;

        // A fragments: h1 = relu(a + c), all in bf16x2
        uint32_t a0[4], a1[4], a2[4], a3[4];
        #pragma unroll
        for (int s = 0; s < 4; s++) {
            uint32_t p = ar[8 * s + tig];        // a at k,k+1
            uint32_t q = ar[8 * s + tig + 4];    // a at k+8,k+9
            a0[s] = relu_bf16x2(add_bf16x2(p, cp0[2 * s + 0]));   // row gid,   k,k+1
            a1[s] = relu_bf16x2(add_bf16x2(p, cp1[2 * s + 0]));   // row gid+8, k,k+1
            a2[s] = relu_bf16x2(add_bf16x2(q, cp0[2 * s + 1]));   // row gid,   k+8,k+9
            a3[s] = relu_bf16x2(add_bf16x2(q, cp1[2 * s + 1]));   // row gid+8, k+8,k+9
        }

        #pragma unroll
        for (int nb = 0; nb < 8; nb++) {
            float2 bg = *reinterpret_cast<const float2*>(s_g1b + nb * 8 + 2 * tig);
            float d0 = bg.x, d1 = bg.y, d2 = bg.x, d3 = bg.y;
            #pragma unroll
            for (int s = 0; s < 4; s++)
                mma_bf16(d0, d1, d2, d3, a0[s], a1[s], a2[s], a3[s],
                         bw[nb][s].x, bw[nb][s].y);
            float2 gw = *reinterpret_cast<const float2*>(s_g2w + nb * 8 + 2 * tig);
            acc0 = fmaf(fmaxf(d0, 0.0f), gw.x, acc0);
            acc0 = fmaf(fmaxf(d1, 0.0f), gw.y, acc0);
            acc1 = fmaf(fmaxf(d2, 0.0f), gw.x, acc1);
            acc1 = fmaf(fmaxf(d3, 0.0f), gw.y, acc1);
        }
    }

    // reduce over the 4 tig lanes (each holds a disjoint j-subset for same i)
    acc0 += __shfl_xor_sync(0xFFFFFFFFu, acc0, 1);
    acc0 += __shfl_xor_sync(0xFFFFFFFFu, acc0, 2);
    acc1 += __shfl_xor_sync(0xFFFFFFFFu, acc1, 1);
    acc1 += __shfl_xor_sync(0xFFFFFFFFu, acc1, 2);

    if (tig == 0) {
        float* dst = g_partial + ((size_t)chunk * BB + b) * NINT + rowl;
        dst[0] = acc0;
        dst[8] = acc1;
    }
}

// ---------------------------------------------------------------------------
// Final reduction: out[b][i] = (sum over chunks) / NBC + G2b
// ---------------------------------------------------------------------------
__global__ void final_kernel(const float* __restrict__ G2b, float* __restrict__ out) {
    int idx = blockIdx.x * blockDim.x + threadIdx.x;   // 0..16383
    int b  = idx >> 12;
    int ii = idx & 4095;
    float s = 0.0f;
    #pragma unroll
    for (int ch = 0; ch < NCHUNK; ch++)
        s += g_partial[((size_t)ch * BB + b) * NINT + ii];
    out[idx] = s * (1.0f / (float)NBC) + G2b[0];
}

// ---------------------------------------------------------------------------
// Launch.  Inputs (metadata order):
// 0 boundary_info 1 interior_coords 2 W0 3 b0 4 W1 5 b1
// 6 G0w 7 G0b 8 G1w 9 G1b 10 G2w 11 G2b 12 interior_h 13 interior_w
// ---------------------------------------------------------------------------
extern "C" void kernel_launch(void* const* d_in, const int* in_sizes, int n_in,
                              void* d_out, int out_size) {
    const float* binfo  = (const float*)d_in[0];
    const float* coords = (const float*)d_in[1];
    const float* W0     = (const float*)d_in[2];
    const float* b0     = (const float*)d_in[3];
    const float* W1     = (const float*)d_in[4];
    const float* b1     = (const float*)d_in[5];
    const float* G0w    = (const float*)d_in[6];
    const float* G0b    = (const float*)d_in[7];
    const float* G1w    = (const float*)d_in[8];
    const float* G1b    = (const float*)d_in[9];
    const float* G2w    = (const float*)d_in[10];
    const float* G2b    = (const float*)d_in[11];
    float* out          = (float*)d_out;

    cudaFuncSetAttribute(main_kernel, cudaFuncAttributeMaxDynamicSharedMemorySize, SMEM_TOTAL);

    prepA_kernel<<<256, 128>>>(binfo, W0, b0, W1, b1, G0w);
    main_kernel<<<dim3(32, BB, NCHUNK), 256, SMEM_TOTAL>>>(G1w, G1b, G2w, coords, G0w, G0b);
    final_kernel<<<BB * NINT / 256, 256>>>(G2b, out);
}

// round 12
// speedup vs baseline: 2.1895x; 1.0886x over previous
#include <cuda_runtime.h>
#include <cstdint>

// Problem constants (fixed by the dataset)
#define BB    4
#define NBC   128
#define NINT  4096
#define HID   64

#define NBC_CHK  64
#define NCHUNK   (NBC / NBC_CHK)      // 2

// ---------------------------------------------------------------------------
// Device scratch (allocation-free)
// ---------------------------------------------------------------------------
__device__ float g_avec[BB * NBC * HID];              // a[b][nbc][k]
__device__ float g_partial[NCHUNK * BB * NINT];       // per-chunk partial sums

// ---------------------------------------------------------------------------
// fp16 helpers (plain sm_80+)
// ---------------------------------------------------------------------------
__device__ __forceinline__ uint32_t pack_f16x2(float lo, float hi) {
    uint32_t r;
    asm("cvt.rn.f16x2.f32 %0, %1, %2;" : "=r"(r) : "f"(hi), "f"(lo));
    return r;
}
__device__ __forceinline__ uint32_t add_f16x2(uint32_t a, uint32_t b) {
    uint32_t r;
    asm("add.f16x2 %0, %1, %2;" : "=r"(r) : "r"(a), "r"(b));
    return r;
}
__device__ __forceinline__ uint32_t relu_f16x2(uint32_t a) {
    uint32_t r;
    asm("max.f16x2 %0, %1, %2;" : "=r"(r) : "r"(a), "r"(0u));
    return r;
}
// f16-accum MMA, C given explicitly (bias fold, no init MOVs)
__device__ __forceinline__ void mma_f16_init(uint32_t& d0, uint32_t& d1,
                                             uint32_t a0, uint32_t a1, uint32_t a2, uint32_t a3,
                                             uint32_t b0, uint32_t b1, uint32_t c) {
    asm volatile("mma.sync.aligned.m16n8k16.row.col.f16.f16.f16.f16 "
                 "{%0,%1}, {%2,%3,%4,%5}, {%6,%7}, {%8,%8};"
                 : "=r"(d0), "=r"(d1)
                 : "r"(a0), "r"(a1), "r"(a2), "r"(a3), "r"(b0), "r"(b1), "r"(c));
}
__device__ __forceinline__ void mma_f16_acc(uint32_t& d0, uint32_t& d1,
                                            uint32_t a0, uint32_t a1, uint32_t a2, uint32_t a3,
                                            uint32_t b0, uint32_t b1) {
    asm volatile("mma.sync.aligned.m16n8k16.row.col.f16.f16.f16.f16 "
                 "{%0,%1}, {%2,%3,%4,%5}, {%6,%7}, {%0,%1};"
                 : "+r"(d0), "+r"(d1)
                 : "r"(a0), "r"(a1), "r"(a2), "r"(a3), "r"(b0), "r"(b1));
}
// f32-accum epilogue MMA (f16 inputs)
__device__ __forceinline__ void mma_f16_f32(float& d0, float& d1, float& d2, float& d3,
                                            uint32_t a0, uint32_t a1, uint32_t a2, uint32_t a3,
                                            uint32_t b0, uint32_t b1) {
    asm volatile("mma.sync.aligned.m16n8k16.row.col.f32.f16.f16.f32 "
                 "{%0,%1,%2,%3}, {%4,%5,%6,%7}, {%8,%9}, {%0,%1,%2,%3};"
                 : "+f"(d0), "+f"(d1), "+f"(d2), "+f"(d3)
                 : "r"(a0), "r"(a1), "r"(a2), "r"(a3), "r"(b0), "r"(b1));
}

__device__ __forceinline__ uint32_t smem_u32(const void* p) {
    uint32_t a;
    asm("{ .reg .u64 t; cvta.to.shared.u64 t, %1; cvt.u32.u64 %0, t; }" : "=r"(a) : "l"(p));
    return a;
}
__device__ __forceinline__ void cp_async16(uint32_t saddr, const void* g) {
    asm volatile("cp.async.cg.shared.global [%0], [%1], 16;" :: "r"(saddr), "l"(g));
}

// ---------------------------------------------------------------------------
// prepA kernel: per (b,nbc): bf = relu(relu(binfo@W0+b0)@W1+b1); a = bf@G0w[:64]
// 256 blocks x 128 threads (2 boundary points per block).
// W1 and G0w prefetched to smem with cp.async, overlapped with stage 0.
// ---------------------------------------------------------------------------
__global__ void __launch_bounds__(128)
prepA_kernel(const float* __restrict__ binfo,
             const float* __restrict__ W0, const float* __restrict__ b0,
             const float* __restrict__ W1, const float* __restrict__ b1,
             const float* __restrict__ G0w) {
    __shared__ __align__(16) float sW1[HID * HID];
    __shared__ __align__(16) float sG0[HID * HID];
    __shared__ float sbf0[2][HID];
    __shared__ float sbf1[2][HID];

    const int tid = threadIdx.x;
    const int sub = tid >> 6;       // 0..1
    const int j   = tid & 63;
    const int bn  = blockIdx.x * 2 + sub;    // 0..511

    {   // async prefetch of big weights (overlaps with stage 0)
        uint32_t sw = smem_u32(sW1);
        uint32_t sg = smem_u32(sG0);
        #pragma unroll
        for (int i = tid; i < 1024; i += 128) cp_async16(sw + i * 16, W1 + i * 4);
        #pragma unroll
        for (int i = tid; i < 1024; i += 128) cp_async16(sg + i * 16, G0w + i * 4);
        asm volatile("cp.async.commit_group;" ::: "memory");
    }

    // stage 0: bf0 = relu(binfo @ W0 + b0)
    const float* bi = binfo + bn * 3;
    float x0 = bi[0], x1 = bi[1], x2 = bi[2];
    sbf0[sub][j] = fmaxf(
        fmaf(x0, W0[j], fmaf(x1, W0[64 + j], fmaf(x2, W0[128 + j], b0[j]))), 0.0f);

    asm volatile("cp.async.wait_group 0;" ::: "memory");
    __syncthreads();

    // stage 1: bf1 = relu(bf0 @ W1 + b1)
    float s = b1[j];
    #pragma unroll 16
    for (int k = 0; k < HID; k++) s = fmaf(sbf0[sub][k], sW1[k * 64 + j], s);
    sbf1[sub][j] = fmaxf(s, 0.0f);
    __syncthreads();

    // stage 2: a = bf1 @ G0w[:64]
    float a = 0.0f;
    #pragma unroll 16
    for (int k = 0; k < HID; k++) a = fmaf(sbf1[sub][k], sG0[k * 64 + j], a);
    g_avec[bn * 64 + j] = a;
}

// ---------------------------------------------------------------------------
// Main kernel: fp16 m16n8k16 with f16 accumulators; bias via C operand;
// second-GEMM epilogue (f16 in, f32 accum). grid (32,4,2)=256 CTAs @ 2/SM.
// ---------------------------------------------------------------------------
#define WSTRIDE 68   // uint2 units per packed row; conflict-free per phase

// smem: s_ap2 64*16 uint2 (8192B) | s_w 16*68 uint2 (8704B) | 3*64 f (768B)
#define SMEM_AP_BYTES 8192
#define SMEM_W_BYTES  (16 * WSTRIDE * 8)
#define SMEM_WX_OFF   (SMEM_AP_BYTES + SMEM_W_BYTES)
#define SMEM_TOTAL    (SMEM_WX_OFF + 3 * 64 * 4)

__global__ void __launch_bounds__(256, 2)
main_kernel(const float* __restrict__ G1w,
            const float* __restrict__ G1b,
            const float* __restrict__ G2w,
            const float* __restrict__ coords,
            const float* __restrict__ G0w,
            const float* __restrict__ G0b) {
    extern __shared__ char smem[];
    uint2* s_ap2 = reinterpret_cast<uint2*>(smem);
    uint2* s_w   = reinterpret_cast<uint2*>(smem + SMEM_AP_BYTES);
    float* s_wx  = reinterpret_cast<float*>(smem + SMEM_WX_OFF);
    float* s_wy  = s_wx + 64;
    float* s_gb  = s_wy + 64;

    const int tid   = threadIdx.x;
    const int wid   = tid >> 5;
    const int lane  = tid & 31;
    const int gid   = lane >> 2;    // 0..7
    const int tig   = lane & 3;     // 0..3
    const int tile  = blockIdx.x;   // 0..31
    const int b     = blockIdx.y;   // 0..3
    const int chunk = blockIdx.z;   // 0..1
    const int rowl  = tile * 128 + wid * 16 + gid;   // local row within batch
    const int row0  = b * NINT + rowl;               // global row (i)

    // --- cooperative smem init ---
    {   // a for this (batch, chunk) packed in A-fragment pair order (fp16)
        const float* abase = g_avec + ((size_t)b * NBC + chunk * NBC_CHK) * HID;
        #pragma unroll
        for (int idx = tid; idx < NBC_CHK * 16; idx += 256) {
            int nn = idx >> 4;
            int p  = idx & 15;
            int s  = p >> 2;
            int t  = p & 3;
            const float* row = abase + nn * 64 + 16 * s + 2 * t;
            float2 lo = *reinterpret_cast<const float2*>(row);
            float2 hi = *reinterpret_cast<const float2*>(row + 8);
            s_ap2[idx] = make_uint2(pack_f16x2(lo.x, lo.y), pack_f16x2(hi.x, hi.y));
        }
    }
    {   // G1w -> fp16, packed per (s,tg): {W[k0],W[k0+1]} , {W[k0+8],W[k0+9]}
        #pragma unroll
        for (int idx = tid; idx < 16 * 64; idx += 256) {
            int prow = idx >> 6;            // 0..15 = s*4 + tg
            int col  = idx & 63;
            int s    = prow >> 2;
            int tg   = prow & 3;
            int k0   = 16 * s + 2 * tg;
            uint32_t w0 = pack_f16x2(G1w[k0 * 64 + col],       G1w[(k0 + 1) * 64 + col]);
            uint32_t w1 = pack_f16x2(G1w[(k0 + 8) * 64 + col], G1w[(k0 + 9) * 64 + col]);
            s_w[prow * WSTRIDE + col] = make_uint2(w0, w1);
        }
    }
    if (tid < 64) {
        s_wx[tid] = G0w[64 * 64 + tid];
        s_wy[tid] = G0w[65 * 64 + tid];
        s_gb[tid] = G0b[tid];
    }
    __syncthreads();

    // --- loop-invariant registers ---
    // c packed f16x2 (rows row0 / row0+8), k-pairs (16s+2tig{,+1}) and (+8{,+9})
    uint32_t cp0[8], cp1[8];
    {
        float cx0 = coords[(size_t)row0 * 2 + 0];
        float cy0 = coords[(size_t)row0 * 2 + 1];
        float cx1 = coords[(size_t)(row0 + 8) * 2 + 0];
        float cy1 = coords[(size_t)(row0 + 8) * 2 + 1];
        #pragma unroll
        for (int s = 0; s < 4; s++) {
            #pragma unroll
            for (int h = 0; h < 2; h++) {
                int k = 16 * s + 2 * tig + 8 * h;
                float wxa = s_wx[k],     wya = s_wy[k],     gba = s_gb[k];
                float wxb = s_wx[k + 1], wyb = s_wy[k + 1], gbb = s_gb[k + 1];
                cp0[2 * s + h] = pack_f16x2(fmaf(cx0, wxa, fmaf(cy0, wya, gba)),
                                            fmaf(cx0, wxb, fmaf(cy0, wyb, gbb)));
                cp1[2 * s + h] = pack_f16x2(fmaf(cx1, wxa, fmaf(cy1, wya, gba)),
                                            fmaf(cx1, wxb, fmaf(cy1, wyb, gbb)));
            }
        }
    }
    // bias C-operands: packed {G1b[8nb+2tig], G1b[8nb+2tig+1]} (same for both rows)
    uint32_t bb[8];
    #pragma unroll
    for (int nb = 0; nb < 8; nb++) {
        float2 g = *reinterpret_cast<const float2*>(G1b + nb * 8 + 2 * tig);
        bb[nb] = pack_f16x2(g.x, g.y);
    }
    // second-GEMM B fragments: g2w as j-rows (k dim), n-replicated
    uint2 b2[4];
    #pragma unroll
    for (int kc = 0; kc < 4; kc++) {
        int k = 16 * kc + 2 * tig;
        float2 glo = *reinterpret_cast<const float2*>(G2w + k);
        float2 ghi = *reinterpret_cast<const float2*>(G2w + k + 8);
        b2[kc] = make_uint2(pack_f16x2(glo.x, glo.y), pack_f16x2(ghi.x, ghi.y));
    }

    // persistent second-GEMM accumulators (2 chains)
    float Da0 = 0.0f, Da1 = 0.0f, Da2 = 0.0f, Da3 = 0.0f;
    float Db0 = 0.0f, Db1 = 0.0f, Db2 = 0.0f, Db3 = 0.0f;

    #pragma unroll 1
    for (int nn = 0; nn < NBC_CHK; nn++) {
        const uint2* ar = s_ap2 + nn * 16;

        // A fragments: h1 = relu(a + c), f16x2
        uint32_t A0[4], A1[4], A2v[4], A3[4];
        #pragma unroll
        for (int s = 0; s < 4; s++) {
            uint2 ap = ar[s * 4 + tig];
            A0[s]  = relu_f16x2(add_f16x2(ap.x, cp0[2 * s + 0]));   // row gid,   k,k+1
            A1[s]  = relu_f16x2(add_f16x2(ap.x, cp1[2 * s + 0]));   // row gid+8, k,k+1
            A2v[s] = relu_f16x2(add_f16x2(ap.y, cp0[2 * s + 1]));   // row gid,   k+8,k+9
            A3[s]  = relu_f16x2(add_f16x2(ap.y, cp1[2 * s + 1]));   // row gid+8, k+8,k+9
        }

        #pragma unroll
        for (int kc = 0; kc < 4; kc++) {
            const int nb0 = 2 * kc, nb1 = 2 * kc + 1;
            uint32_t d0, d1, f0, f1;
            {
                uint2 w = s_w[tig * WSTRIDE + nb0 * 8 + gid];
                mma_f16_init(d0, d1, A0[0], A1[0], A2v[0], A3[0], w.x, w.y, bb[nb0]);
                #pragma unroll
                for (int s = 1; s < 4; s++) {
                    uint2 ws = s_w[(s * 4 + tig) * WSTRIDE + nb0 * 8 + gid];
                    mma_f16_acc(d0, d1, A0[s], A1[s], A2v[s], A3[s], ws.x, ws.y);
                }
            }
            {
                uint2 w = s_w[tig * WSTRIDE + nb1 * 8 + gid];
                mma_f16_init(f0, f1, A0[0], A1[0], A2v[0], A3[0], w.x, w.y, bb[nb1]);
                #pragma unroll
                for (int s = 1; s < 4; s++) {
                    uint2 ws = s_w[(s * 4 + tig) * WSTRIDE + nb1 * 8 + gid];
                    mma_f16_acc(f0, f1, A0[s], A1[s], A2v[s], A3[s], ws.x, ws.y);
                }
            }
            // relu(h2) -> epilogue A fragments (layout matches directly)
            d0 = relu_f16x2(d0);   // (row gid,   j 16kc+2tig,+1)
            d1 = relu_f16x2(d1);   // (row gid+8, j 16kc+2tig,+1)
            f0 = relu_f16x2(f0);   // (row gid,   j 16kc+8+2tig,+9)
            f1 = relu_f16x2(f1);   // (row gid+8, ...)
            if (kc & 1)
                mma_f16_f32(Db0, Db1, Db2, Db3, d0, d1, f0, f1, b2[kc].x, b2[kc].y);
            else
                mma_f16_f32(Da0, Da1, Da2, Da3, d0, d1, f0, f1, b2[kc].x, b2[kc].y);
        }
    }

    // D2 n-columns are identical (B replicated over n) -> no reduction needed.
    if (tig == 0) {
        float* dst = g_partial + ((size_t)chunk * BB + b) * NINT + rowl;
        dst[0] = Da0 + Db0;     // row gid
        dst[8] = Da2 + Db2;     // row gid+8
    }
}

// ---------------------------------------------------------------------------
// Final reduction: out[b][i] = (sum over chunks) / NBC + G2b
// ---------------------------------------------------------------------------
__global__ void final_kernel(const float* __restrict__ G2b, float* __restrict__ out) {
    int idx = blockIdx.x * blockDim.x + threadIdx.x;   // 0..16383
    int b  = idx >> 12;
    int ii = idx & 4095;
    float s = 0.0f;
    #pragma unroll
    for (int ch = 0; ch < NCHUNK; ch++)
        s += g_partial[((size_t)ch * BB + b) * NINT + ii];
    out[idx] = s * (1.0f / (float)NBC) + G2b[0];
}

// ---------------------------------------------------------------------------
// Launch.  Inputs (metadata order):
// 0 boundary_info 1 interior_coords 2 W0 3 b0 4 W1 5 b1
// 6 G0w 7 G0b 8 G1w 9 G1b 10 G2w 11 G2b 12 interior_h 13 interior_w
// ---------------------------------------------------------------------------
extern "C" void kernel_launch(void* const* d_in, const int* in_sizes, int n_in,
                              void* d_out, int out_size) {
    const float* binfo  = (const float*)d_in[0];
    const float* coords = (const float*)d_in[1];
    const float* W0     = (const float*)d_in[2];
    const float* b0     = (const float*)d_in[3];
    const float* W1     = (const float*)d_in[4];
    const float* b1     = (const float*)d_in[5];
    const float* G0w    = (const float*)d_in[6];
    const float* G0b    = (const float*)d_in[7];
    const float* G1w    = (const float*)d_in[8];
    const float* G1b    = (const float*)d_in[9];
    const float* G2w    = (const float*)d_in[10];
    const float* G2b    = (const float*)d_in[11];
    float* out          = (float*)d_out;

    cudaFuncSetAttribute(main_kernel, cudaFuncAttributeMaxDynamicSharedMemorySize, SMEM_TOTAL);

    prepA_kernel<<<256, 128>>>(binfo, W0, b0, W1, b1, G0w);
    main_kernel<<<dim3(32, BB, NCHUNK), 256, SMEM_TOTAL>>>(G1w, G1b, G2w, coords, G0w, G0b);
    final_kernel<<<BB * NINT / 256, 256>>>(G2b, out);
}

// round 13
// speedup vs baseline: 2.2536x; 1.0293x over previous
#include <cuda_runtime.h>
#include <cstdint>

// Problem constants (fixed by the dataset)
#define BB    4
#define NBC   128
#define NINT  4096
#define HID   64

#define NBC_CHK  64
#define NCHUNK   (NBC / NBC_CHK)      // 2

// ---------------------------------------------------------------------------
// Device scratch (allocation-free)
// ---------------------------------------------------------------------------
__device__ float g_avec[BB * NBC * HID];              // a[b][nbc][k]

// ---------------------------------------------------------------------------
// fp16 helpers (plain sm_80+)
// ---------------------------------------------------------------------------
__device__ __forceinline__ uint32_t pack_f16x2(float lo, float hi) {
    uint32_t r;
    asm("cvt.rn.f16x2.f32 %0, %1, %2;" : "=r"(r) : "f"(hi), "f"(lo));
    return r;
}
__device__ __forceinline__ uint32_t add_f16x2(uint32_t a, uint32_t b) {
    uint32_t r;
    asm("add.f16x2 %0, %1, %2;" : "=r"(r) : "r"(a), "r"(b));
    return r;
}
__device__ __forceinline__ uint32_t relu_f16x2(uint32_t a) {
    uint32_t r;
    asm("max.f16x2 %0, %1, %2;" : "=r"(r) : "r"(a), "r"(0u));
    return r;
}
// f16-accum MMA, C given explicitly (bias fold, no init MOVs)
__device__ __forceinline__ void mma_f16_init(uint32_t& d0, uint32_t& d1,
                                             uint32_t a0, uint32_t a1, uint32_t a2, uint32_t a3,
                                             uint32_t b0, uint32_t b1, uint32_t c) {
    asm volatile("mma.sync.aligned.m16n8k16.row.col.f16.f16.f16.f16 "
                 "{%0,%1}, {%2,%3,%4,%5}, {%6,%7}, {%8,%8};"
                 : "=r"(d0), "=r"(d1)
                 : "r"(a0), "r"(a1), "r"(a2), "r"(a3), "r"(b0), "r"(b1), "r"(c));
}
__device__ __forceinline__ void mma_f16_acc(uint32_t& d0, uint32_t& d1,
                                            uint32_t a0, uint32_t a1, uint32_t a2, uint32_t a3,
                                            uint32_t b0, uint32_t b1) {
    asm volatile("mma.sync.aligned.m16n8k16.row.col.f16.f16.f16.f16 "
                 "{%0,%1}, {%2,%3,%4,%5}, {%6,%7}, {%0,%1};"
                 : "+r"(d0), "+r"(d1)
                 : "r"(a0), "r"(a1), "r"(a2), "r"(a3), "r"(b0), "r"(b1));
}
// f32-accum epilogue MMA (f16 inputs)
__device__ __forceinline__ void mma_f16_f32(float& d0, float& d1, float& d2, float& d3,
                                            uint32_t a0, uint32_t a1, uint32_t a2, uint32_t a3,
                                            uint32_t b0, uint32_t b1) {
    asm volatile("mma.sync.aligned.m16n8k16.row.col.f32.f16.f16.f32 "
                 "{%0,%1,%2,%3}, {%4,%5,%6,%7}, {%8,%9}, {%0,%1,%2,%3};"
                 : "+f"(d0), "+f"(d1), "+f"(d2), "+f"(d3)
                 : "r"(a0), "r"(a1), "r"(a2), "r"(a3), "r"(b0), "r"(b1));
}

__device__ __forceinline__ uint32_t smem_u32(const void* p) {
    uint32_t a;
    asm("{ .reg .u64 t; cvta.to.shared.u64 t, %1; cvt.u32.u64 %0, t; }" : "=r"(a) : "l"(p));
    return a;
}
__device__ __forceinline__ void cp_async16(uint32_t saddr, const void* g) {
    asm volatile("cp.async.cg.shared.global [%0], [%1], 16;" :: "r"(saddr), "l"(g));
}

// ---------------------------------------------------------------------------
// prepA kernel: per (b,nbc): bf = relu(relu(binfo@W0+b0)@W1+b1); a = bf@G0w[:64]
// 256 blocks x 128 threads (2 boundary points per block).
// Also zeroes d_out (64 floats per block) for the atomic accumulation in main.
// ---------------------------------------------------------------------------
__global__ void __launch_bounds__(128)
prepA_kernel(const float* __restrict__ binfo,
             const float* __restrict__ W0, const float* __restrict__ b0,
             const float* __restrict__ W1, const float* __restrict__ b1,
             const float* __restrict__ G0w,
             float* __restrict__ out) {
    __shared__ __align__(16) float sW1[HID * HID];
    __shared__ __align__(16) float sG0[HID * HID];
    __shared__ float sbf0[2][HID];
    __shared__ float sbf1[2][HID];

    const int tid = threadIdx.x;
    const int sub = tid >> 6;       // 0..1
    const int j   = tid & 63;
    const int bn  = blockIdx.x * 2 + sub;    // 0..511

    {   // async prefetch of big weights (overlaps with stage 0)
        uint32_t sw = smem_u32(sW1);
        uint32_t sg = smem_u32(sG0);
        #pragma unroll
        for (int i = tid; i < 1024; i += 128) cp_async16(sw + i * 16, W1 + i * 4);
        #pragma unroll
        for (int i = tid; i < 1024; i += 128) cp_async16(sg + i * 16, G0w + i * 4);
        asm volatile("cp.async.commit_group;" ::: "memory");
    }

    // zero the output slice this block owns (BB*NINT = 16384 = 256 blocks * 64)
    if (tid < 64) out[blockIdx.x * 64 + tid] = 0.0f;

    // stage 0: bf0 = relu(binfo @ W0 + b0)
    const float* bi = binfo + bn * 3;
    float x0 = bi[0], x1 = bi[1], x2 = bi[2];
    sbf0[sub][j] = fmaxf(
        fmaf(x0, W0[j], fmaf(x1, W0[64 + j], fmaf(x2, W0[128 + j], b0[j]))), 0.0f);

    asm volatile("cp.async.wait_group 0;" ::: "memory");
    __syncthreads();

    // stage 1: bf1 = relu(bf0 @ W1 + b1)
    float s = b1[j];
    #pragma unroll 16
    for (int k = 0; k < HID; k++) s = fmaf(sbf0[sub][k], sW1[k * 64 + j], s);
    sbf1[sub][j] = fmaxf(s, 0.0f);
    __syncthreads();

    // stage 2: a = bf1 @ G0w[:64]
    float a = 0.0f;
    #pragma unroll 16
    for (int k = 0; k < HID; k++) a = fmaf(sbf1[sub][k], sG0[k * 64 + j], a);
    g_avec[bn * 64 + j] = a;
}

// ---------------------------------------------------------------------------
// Main kernel: fp16 m16n8k16 with f16 accumulators; bias via C operand;
// second-GEMM epilogue (f16 in, f32 accum); results atomically added to out
// (each chunk contributes acc/NBC + G2b/NCHUNK; 2 fp32 addends -> bit-exact
// regardless of order). grid (32,4,2)=256 CTAs @ 2/SM.
// ---------------------------------------------------------------------------
#define WSTRIDE 68   // uint2 units per packed row; conflict-free per phase

// smem: s_ap2 64*16 uint2 (8192B) | s_w 16*68 uint2 (8704B) | 3*64 f (768B)
#define SMEM_AP_BYTES 8192
#define SMEM_W_BYTES  (16 * WSTRIDE * 8)
#define SMEM_WX_OFF   (SMEM_AP_BYTES + SMEM_W_BYTES)
#define SMEM_TOTAL    (SMEM_WX_OFF + 3 * 64 * 4)

__global__ void __launch_bounds__(256, 2)
main_kernel(const float* __restrict__ G1w,
            const float* __restrict__ G1b,
            const float* __restrict__ G2w,
            const float* __restrict__ G2b,
            const float* __restrict__ coords,
            const float* __restrict__ G0w,
            const float* __restrict__ G0b,
            float* __restrict__ out) {
    extern __shared__ char smem[];
    uint2* s_ap2 = reinterpret_cast<uint2*>(smem);
    uint2* s_w   = reinterpret_cast<uint2*>(smem + SMEM_AP_BYTES);
    float* s_wx  = reinterpret_cast<float*>(smem + SMEM_WX_OFF);
    float* s_wy  = s_wx + 64;
    float* s_gb  = s_wy + 64;

    const int tid   = threadIdx.x;
    const int wid   = tid >> 5;
    const int lane  = tid & 31;
    const int gid   = lane >> 2;    // 0..7
    const int tig   = lane & 3;     // 0..3
    const int tile  = blockIdx.x;   // 0..31
    const int b     = blockIdx.y;   // 0..3
    const int chunk = blockIdx.z;   // 0..1
    const int rowl  = tile * 128 + wid * 16 + gid;   // local row within batch
    const int row0  = b * NINT + rowl;               // global row (i)

    // --- cooperative smem init ---
    {   // a for this (batch, chunk) packed in A-fragment pair order (fp16)
        const float* abase = g_avec + ((size_t)b * NBC + chunk * NBC_CHK) * HID;
        #pragma unroll
        for (int idx = tid; idx < NBC_CHK * 16; idx += 256) {
            int nn = idx >> 4;
            int p  = idx & 15;
            int s  = p >> 2;
            int t  = p & 3;
            const float* row = abase + nn * 64 + 16 * s + 2 * t;
            float2 lo = *reinterpret_cast<const float2*>(row);
            float2 hi = *reinterpret_cast<const float2*>(row + 8);
            s_ap2[idx] = make_uint2(pack_f16x2(lo.x, lo.y), pack_f16x2(hi.x, hi.y));
        }
    }
    {   // G1w -> fp16, packed per (s,tg): {W[k0],W[k0+1]} , {W[k0+8],W[k0+9]}
        #pragma unroll
        for (int idx = tid; idx < 16 * 64; idx += 256) {
            int prow = idx >> 6;            // 0..15 = s*4 + tg
            int col  = idx & 63;
            int s    = prow >> 2;
            int tg   = prow & 3;
            int k0   = 16 * s + 2 * tg;
            uint32_t w0 = pack_f16x2(G1w[k0 * 64 + col],       G1w[(k0 + 1) * 64 + col]);
            uint32_t w1 = pack_f16x2(G1w[(k0 + 8) * 64 + col], G1w[(k0 + 9) * 64 + col]);
            s_w[prow * WSTRIDE + col] = make_uint2(w0, w1);
        }
    }
    if (tid < 64) {
        s_wx[tid] = G0w[64 * 64 + tid];
        s_wy[tid] = G0w[65 * 64 + tid];
        s_gb[tid] = G0b[tid];
    }
    __syncthreads();

    // --- loop-invariant registers ---
    // c packed f16x2 (rows row0 / row0+8), k-pairs (16s+2tig{,+1}) and (+8{,+9})
    uint32_t cp0[8], cp1[8];
    {
        float cx0 = coords[(size_t)row0 * 2 + 0];
        float cy0 = coords[(size_t)row0 * 2 + 1];
        float cx1 = coords[(size_t)(row0 + 8) * 2 + 0];
        float cy1 = coords[(size_t)(row0 + 8) * 2 + 1];
        #pragma unroll
        for (int s = 0; s < 4; s++) {
            #pragma unroll
            for (int h = 0; h < 2; h++) {
                int k = 16 * s + 2 * tig + 8 * h;
                float wxa = s_wx[k],     wya = s_wy[k],     gba = s_gb[k];
                float wxb = s_wx[k + 1], wyb = s_wy[k + 1], gbb = s_gb[k + 1];
                cp0[2 * s + h] = pack_f16x2(fmaf(cx0, wxa, fmaf(cy0, wya, gba)),
                                            fmaf(cx0, wxb, fmaf(cy0, wyb, gbb)));
                cp1[2 * s + h] = pack_f16x2(fmaf(cx1, wxa, fmaf(cy1, wya, gba)),
                                            fmaf(cx1, wxb, fmaf(cy1, wyb, gbb)));
            }
        }
    }
    // bias C-operands: packed {G1b[8nb+2tig], G1b[8nb+2tig+1]}
    uint32_t bb[8];
    #pragma unroll
    for (int nb = 0; nb < 8; nb++) {
        float2 g = *reinterpret_cast<const float2*>(G1b + nb * 8 + 2 * tig);
        bb[nb] = pack_f16x2(g.x, g.y);
    }
    // second-GEMM B fragments: g2w as j-rows (k dim), n-replicated
    uint2 b2[4];
    #pragma unroll
    for (int kc = 0; kc < 4; kc++) {
        int k = 16 * kc + 2 * tig;
        float2 glo = *reinterpret_cast<const float2*>(G2w + k);
        float2 ghi = *reinterpret_cast<const float2*>(G2w + k + 8);
        b2[kc] = make_uint2(pack_f16x2(glo.x, glo.y), pack_f16x2(ghi.x, ghi.y));
    }
    // hoist B fragments for nb 0..1 into registers (16 regs)
    uint2 bwr[2][4];
    #pragma unroll
    for (int nb = 0; nb < 2; nb++)
        #pragma unroll
        for (int s = 0; s < 4; s++)
            bwr[nb][s] = s_w[(s * 4 + tig) * WSTRIDE + nb * 8 + gid];

    // persistent second-GEMM accumulators (2 chains)
    float Da0 = 0.0f, Da1 = 0.0f, Da2 = 0.0f, Da3 = 0.0f;
    float Db0 = 0.0f, Db1 = 0.0f, Db2 = 0.0f, Db3 = 0.0f;

    #pragma unroll 1
    for (int nn = 0; nn < NBC_CHK; nn++) {
        const uint2* ar = s_ap2 + nn * 16;

        // A fragments: h1 = relu(a + c), f16x2
        uint32_t A0[4], A1[4], A2v[4], A3[4];
        #pragma unroll
        for (int s = 0; s < 4; s++) {
            uint2 ap = ar[s * 4 + tig];
            A0[s]  = relu_f16x2(add_f16x2(ap.x, cp0[2 * s + 0]));   // row gid,   k,k+1
            A1[s]  = relu_f16x2(add_f16x2(ap.x, cp1[2 * s + 0]));   // row gid+8, k,k+1
            A2v[s] = relu_f16x2(add_f16x2(ap.y, cp0[2 * s + 1]));   // row gid,   k+8,k+9
            A3[s]  = relu_f16x2(add_f16x2(ap.y, cp1[2 * s + 1]));   // row gid+8, k+8,k+9
        }

        #pragma unroll
        for (int kc = 0; kc < 4; kc++) {
            const int nb0 = 2 * kc, nb1 = 2 * kc + 1;
            uint32_t d0, d1, f0, f1;
            {
                uint2 w = (nb0 < 2) ? bwr[nb0][0] : s_w[tig * WSTRIDE + nb0 * 8 + gid];
                mma_f16_init(d0, d1, A0[0], A1[0], A2v[0], A3[0], w.x, w.y, bb[nb0]);
                #pragma unroll
                for (int s = 1; s < 4; s++) {
                    uint2 ws = (nb0 < 2) ? bwr[nb0][s]
                                         : s_w[(s * 4 + tig) * WSTRIDE + nb0 * 8 + gid];
                    mma_f16_acc(d0, d1, A0[s], A1[s], A2v[s], A3[s], ws.x, ws.y);
                }
            }
            {
                uint2 w = (nb1 < 2) ? bwr[nb1][0] : s_w[tig * WSTRIDE + nb1 * 8 + gid];
                mma_f16_init(f0, f1, A0[0], A1[0], A2v[0], A3[0], w.x, w.y, bb[nb1]);
                #pragma unroll
                for (int s = 1; s < 4; s++) {
                    uint2 ws = (nb1 < 2) ? bwr[nb1][s]
                                         : s_w[(s * 4 + tig) * WSTRIDE + nb1 * 8 + gid];
                    mma_f16_acc(f0, f1, A0[s], A1[s], A2v[s], A3[s], ws.x, ws.y);
                }
            }
            // relu(h2) -> epilogue A fragments (layout matches directly)
            d0 = relu_f16x2(d0);
            d1 = relu_f16x2(d1);
            f0 = relu_f16x2(f0);
            f1 = relu_f16x2(f1);
            if (kc & 1)
                mma_f16_f32(Db0, Db1, Db2, Db3, d0, d1, f0, f1, b2[kc].x, b2[kc].y);
            else
                mma_f16_f32(Da0, Da1, Da2, Da3, d0, d1, f0, f1, b2[kc].x, b2[kc].y);
        }
    }

    // D2 n-columns identical (B replicated) -> no reduction; atomically merge
    // the two nbc-chunks directly into out.
    if (tig == 0) {
        const float scale = 1.0f / (float)NBC;
        const float gb2   = G2b[0] * (1.0f / (float)NCHUNK);
        atomicAdd(out + row0,     fmaf(Da0 + Db0, scale, gb2));
        atomicAdd(out + row0 + 8, fmaf(Da2 + Db2, scale, gb2));
    }
}

// ---------------------------------------------------------------------------
// Launch.  Inputs (metadata order):
// 0 boundary_info 1 interior_coords 2 W0 3 b0 4 W1 5 b1
// 6 G0w 7 G0b 8 G1w 9 G1b 10 G2w 11 G2b 12 interior_h 13 interior_w
// ---------------------------------------------------------------------------
extern "C" void kernel_launch(void* const* d_in, const int* in_sizes, int n_in,
                              void* d_out, int out_size) {
    const float* binfo  = (const float*)d_in[0];
    const float* coords = (const float*)d_in[1];
    const float* W0     = (const float*)d_in[2];
    const float* b0     = (const float*)d_in[3];
    const float* W1     = (const float*)d_in[4];
    const float* b1     = (const float*)d_in[5];
    const float* G0w    = (const float*)d_in[6];
    const float* G0b    = (const float*)d_in[7];
    const float* G1w    = (const float*)d_in[8];
    const float* G1b    = (const float*)d_in[9];
    const float* G2w    = (const float*)d_in[10];
    const float* G2b    = (const float*)d_in[11];
    float* out          = (float*)d_out;

    cudaFuncSetAttribute(main_kernel, cudaFuncAttributeMaxDynamicSharedMemorySize, SMEM_TOTAL);

    prepA_kernel<<<256, 128>>>(binfo, W0, b0, W1, b1, G0w, out);
    main_kernel<<<dim3(32, BB, NCHUNK), 256, SMEM_TOTAL>>>(
        G1w, G1b, G2w, G2b, coords, G0w, G0b, out);
}